// round 8
// baseline (speedup 1.0000x reference)
#include <cuda_runtime.h>
#include <cuda_bf16.h>
#include <cstdint>
#include <math.h>

// ============================================================
// R8: software-pipelined flash attention. Per sync window:
//   QK(j+1) -> sacc_next  (independent tensor work)
//   softmax(j) on sacc_cur (latency hidden behind QK MMAs)
//   PV(j) -> oacc
// mma.sync m16n8k16 bf16 hi/lo 3-term. K/V pre-converted to
// padded tile images (device scratch); separate 2-stage K and V
// smem rings (K consumed one iter early). Q-lo frags in smem.
// Scale tile read from gmem (L2-resident across bh).
// ============================================================

constexpr int kS = 2048, kD = 128, kBQ = 128, kBK = 64;
constexpr int kThreads = 256;
constexpr int kIters = kS / kBK;            // 32
constexpr int kQTiles = kS / kBQ;           // 16

constexpr int kStrideB = 272;               // 136 bf16/row (ldmatrix conflict-free)
constexpr int kHalfB   = 64 * kStrideB;     // 17408 (one hi or lo 64x128 tile)
constexpr int kStageB  = 2 * kHalfB;        // 34816 (hi+lo)
constexpr int kBlobB   = 4 * kHalfB;        // 69632 (g_kv: khi,klo,vhi,vlo)

constexpr int SM_K   = 0;                   // 2 K stages
constexpr int SM_V   = 2 * kStageB;         // 69632, 2 V stages
constexpr int SM_QHI = 4 * kStageB;         // 139264 (128 rows x 272B)
constexpr int SM_QLO = SM_QHI + kStageB;    // 174080
constexpr int kSmemBytes = SM_QLO + kStageB;// 208896

__device__ __align__(16) unsigned char g_kv[32u * 32u * (unsigned)kBlobB];

__device__ __forceinline__ uint32_t smem_u32(const void* p) {
    uint32_t a;
    asm("{ .reg .u64 t; cvta.to.shared.u64 t, %1; cvt.u32.u64 %0, t; }" : "=r"(a) : "l"(p));
    return a;
}
__device__ __forceinline__ void cp16(uint32_t dst, const void* src) {
    asm volatile("cp.async.cg.shared.global [%0], [%1], 16;" :: "r"(dst), "l"(src));
}
__device__ __forceinline__ void cp_commit() { asm volatile("cp.async.commit_group;" ::: "memory"); }
__device__ __forceinline__ void cp_wait0()  { asm volatile("cp.async.wait_group 0;" ::: "memory"); }

__device__ __forceinline__ void ldsm_x4(uint32_t& r0, uint32_t& r1, uint32_t& r2, uint32_t& r3,
                                        uint32_t addr) {
    asm volatile("ldmatrix.sync.aligned.m8n8.x4.shared.b16 {%0,%1,%2,%3}, [%4];"
        : "=r"(r0), "=r"(r1), "=r"(r2), "=r"(r3) : "r"(addr));
}
__device__ __forceinline__ void ldsm_x4_t(uint32_t& r0, uint32_t& r1, uint32_t& r2, uint32_t& r3,
                                          uint32_t addr) {
    asm volatile("ldmatrix.sync.aligned.m8n8.x4.trans.shared.b16 {%0,%1,%2,%3}, [%4];"
        : "=r"(r0), "=r"(r1), "=r"(r2), "=r"(r3) : "r"(addr));
}
__device__ __forceinline__ void mma_bf16(float* d, const uint32_t* a, uint32_t b0, uint32_t b1) {
    asm volatile("mma.sync.aligned.m16n8k16.row.col.f32.bf16.bf16.f32 "
        "{%0,%1,%2,%3}, {%4,%5,%6,%7}, {%8,%9}, {%0,%1,%2,%3};"
        : "+f"(d[0]), "+f"(d[1]), "+f"(d[2]), "+f"(d[3])
        : "r"(a[0]), "r"(a[1]), "r"(a[2]), "r"(a[3]), "r"(b0), "r"(b1));
}
__device__ __forceinline__ uint32_t packbf(float a, float b) {
    __nv_bfloat162 t = __floats2bfloat162_rn(a, b);
    return *reinterpret_cast<uint32_t*>(&t);
}
__device__ __forceinline__ void split2(float a, float b, uint32_t& hi, uint32_t& lo) {
    __nv_bfloat16 ah = __float2bfloat16(a), bh = __float2bfloat16(b);
    __nv_bfloat162 h; h.x = ah; h.y = bh;
    hi = *reinterpret_cast<uint32_t*>(&h);
    lo = packbf(a - __bfloat162float(ah), b - __bfloat162float(bh));
}
__device__ __forceinline__ float decode_scalar(const void* p) {
    const int w = *reinterpret_cast<const int*>(p);
    if (w > -(1 << 23) && w < (1 << 23)) return (float)w;
    return __int_as_float(w);
}

// ---------------- precompute: K,V -> bf16 hi/lo padded tile images ----------------
__global__ __launch_bounds__(256, 4)
void convert_kv_kernel(const float* __restrict__ k, const float* __restrict__ v) {
    const int kt = (int)blockIdx.x, bh = (int)blockIdx.y, tid = (int)threadIdx.x;
    unsigned char* blob = g_kv + (size_t)(bh * 32 + kt) * kBlobB;
    const float* kgt = k + ((size_t)bh * kS + (size_t)kt * kBK) * kD;
    const float* vgt = v + ((size_t)bh * kS + (size_t)kt * kBK) * kD;
    #pragma unroll
    for (int it = 0; it < 8; ++it) {
        const int idx = it * 256 + tid;
        const int r = idx >> 5, c = (idx & 31) << 2;
        const int so = r * kStrideB + c * 2;
        {
            const float4 x = reinterpret_cast<const float4*>(kgt)[idx];
            uint32_t h0, l0, h1, l1;
            split2(x.x, x.y, h0, l0);
            split2(x.z, x.w, h1, l1);
            *reinterpret_cast<uint2*>(blob + so)          = make_uint2(h0, h1);
            *reinterpret_cast<uint2*>(blob + kHalfB + so) = make_uint2(l0, l1);
        }
        {
            const float4 x = reinterpret_cast<const float4*>(vgt)[idx];
            uint32_t h0, l0, h1, l1;
            split2(x.x, x.y, h0, l0);
            split2(x.z, x.w, h1, l1);
            *reinterpret_cast<uint2*>(blob + 2 * kHalfB + so) = make_uint2(h0, h1);
            *reinterpret_cast<uint2*>(blob + 3 * kHalfB + so) = make_uint2(l0, l1);
        }
    }
}

// ---------------- main kernel ----------------
__global__ __launch_bounds__(kThreads, 1)
void flash_mma_kernel(const float* __restrict__ q,
                      const float* __restrict__ sf,
                      const void*  __restrict__ dropout_p,
                      float* __restrict__ out) {
    extern __shared__ char smem[];
    const uint32_t sb = smem_u32(smem);
    const int tid  = (int)threadIdx.x;
    const int wid  = tid >> 5;
    const int lane = tid & 31;
    const int g    = lane >> 2;
    const int t    = lane & 3;
    const int w8   = lane & 7;
    const int b3   = (lane >> 3) & 1;
    const int b4   = (lane >> 4) & 1;
    const int qt = (int)blockIdx.x;
    const int bh = (int)blockIdx.y;

    auto issueK = [&](int kt) {
        const unsigned char* src = g_kv + (size_t)(bh * 32 + kt) * kBlobB;
        const uint32_t dst = sb + SM_K + (uint32_t)(kt & 1) * kStageB;
        #pragma unroll
        for (int i = 0; i < 9; ++i) {
            const int op = i * kThreads + tid;      // 2176 ops of 16B
            if (op < 2176) cp16(dst + op * 16, src + (size_t)op * 16);
        }
    };
    auto issueV = [&](int kt) {
        const unsigned char* src = g_kv + (size_t)(bh * 32 + kt) * kBlobB + kStageB;
        const uint32_t dst = sb + SM_V + (uint32_t)(kt & 1) * kStageB;
        #pragma unroll
        for (int i = 0; i < 9; ++i) {
            const int op = i * kThreads + tid;
            if (op < 2176) cp16(dst + op * 16, src + (size_t)op * 16);
        }
    };

    // prologue copies: {K0,V0}, {K1}
    issueK(0); issueV(0); cp_commit();
    issueK(1); cp_commit();

    // Q -> bf16 hi/lo smem (cooperative)
    const float* qg = q + ((size_t)bh * kS + (size_t)qt * kBQ) * kD;
    #pragma unroll
    for (int it = 0; it < 16; ++it) {
        const int idx = it * kThreads + tid;        // 4096 float4
        const int r = idx >> 5, c = (idx & 31) << 2;
        const float4 x = reinterpret_cast<const float4*>(qg)[idx];
        uint32_t h0, l0, h1, l1;
        split2(x.x, x.y, h0, l0);
        split2(x.z, x.w, h1, l1);
        const int so = r * kStrideB + c * 2;
        *reinterpret_cast<uint2*>(smem + SM_QHI + so) = make_uint2(h0, h1);
        *reinterpret_cast<uint2*>(smem + SM_QLO + so) = make_uint2(l0, l1);
    }
    cp_wait0();
    __syncthreads();

    // Q-hi A-fragments into registers via ldmatrix
    uint32_t qhi[8][4];
    #pragma unroll
    for (int ks = 0; ks < 8; ++ks) {
        const uint32_t addr = sb + SM_QHI +
            (uint32_t)((wid * 16 + w8 + b3 * 8) * kStrideB + (ks * 16 + b4 * 8) * 2);
        ldsm_x4(qhi[ks][0], qhi[ks][1], qhi[ks][2], qhi[ks][3], addr);
    }

    // QK block: 3-term, qlo A-frags streamed from smem
    auto qk_block = [&](float (&sacc)[8][4], int ktile) {
        const uint32_t KH = sb + SM_K + (uint32_t)(ktile & 1) * kStageB;
        const uint32_t KL = KH + kHalfB;
        #pragma unroll
        for (int n = 0; n < 8; ++n)
            #pragma unroll
            for (int c = 0; c < 4; ++c) sacc[n][c] = 0.f;
        #pragma unroll
        for (int ks = 0; ks < 8; ++ks) {
            uint32_t qf[4];
            ldsm_x4(qf[0], qf[1], qf[2], qf[3],
                    sb + SM_QLO + (uint32_t)((wid * 16 + w8 + b3 * 8) * kStrideB
                                             + (ks * 16 + b4 * 8) * 2));
            uint32_t bhi[8][2], blo[8][2];
            #pragma unroll
            for (int p = 0; p < 4; ++p) {
                const uint32_t off = (uint32_t)((p * 16 + b4 * 8 + w8) * kStrideB
                                                + (ks * 16 + b3 * 8) * 2);
                ldsm_x4(bhi[2*p][0], bhi[2*p][1], bhi[2*p+1][0], bhi[2*p+1][1], KH + off);
                ldsm_x4(blo[2*p][0], blo[2*p][1], blo[2*p+1][0], blo[2*p+1][1], KL + off);
            }
            #pragma unroll
            for (int n = 0; n < 8; ++n) {
                mma_bf16(sacc[n], qhi[ks], bhi[n][0], bhi[n][1]);
                mma_bf16(sacc[n], qhi[ks], blo[n][0], blo[n][1]);
                mma_bf16(sacc[n], qf,      bhi[n][0], bhi[n][1]);
            }
        }
    };

    float oacc[16][4];
    #pragma unroll
    for (int n = 0; n < 16; ++n)
        #pragma unroll
        for (int c = 0; c < 4; ++c) oacc[n][c] = 0.f;
    float m0 = -INFINITY, m1 = -INFINITY, l0 = 0.f, l1 = 0.f;

    const float* scr0 = sf + ((size_t)(qt * kBQ) + (size_t)(wid * 16 + g)) * kS + 2 * t;
    const float* scr1 = scr0 + (size_t)8 * kS;

    float saccA[8][4], saccB[8][4];
    qk_block(saccA, 0);     // QK(0)

    auto body = [&](int j, float (&cur)[8][4], float (&nxt)[8][4]) {
        cp_wait0();
        __syncthreads();    // {K(j+1),V(j)} visible; all warps done with stages being reused
        if (j + 2 < kIters) issueK(j + 2);
        if (j + 1 < kIters) { issueV(j + 1); cp_commit(); }

        // ---- QK(j+1) -> nxt (dummy re-compute of tile 31 on last iter; discarded) ----
        qk_block(nxt, (j + 1 < kIters) ? (j + 1) : (kIters - 1));

        // ---- softmax(j) on cur (independent of the QK above) ----
        const float* scg0 = scr0 + (size_t)j * kBK;
        const float* scg1 = scr1 + (size_t)j * kBK;
        float2 sc0[8], sc1[8];
        #pragma unroll
        for (int n = 0; n < 8; ++n) {
            sc0[n] = *reinterpret_cast<const float2*>(scg0 + n * 8);
            sc1[n] = *reinterpret_cast<const float2*>(scg1 + n * 8);
        }
        float mx0 = -INFINITY, mx1 = -INFINITY;
        #pragma unroll
        for (int n = 0; n < 8; ++n) {
            cur[n][0] *= sc0[n].x; cur[n][1] *= sc0[n].y;
            cur[n][2] *= sc1[n].x; cur[n][3] *= sc1[n].y;
            mx0 = fmaxf(mx0, fmaxf(cur[n][0], cur[n][1]));
            mx1 = fmaxf(mx1, fmaxf(cur[n][2], cur[n][3]));
        }
        #pragma unroll
        for (int off = 1; off <= 2; off <<= 1) {
            mx0 = fmaxf(mx0, __shfl_xor_sync(0xffffffffu, mx0, off));
            mx1 = fmaxf(mx1, __shfl_xor_sync(0xffffffffu, mx1, off));
        }
        const float m0n = fmaxf(m0, mx0), m1n = fmaxf(m1, mx1);
        const float a0 = __expf(m0 - m0n), a1 = __expf(m1 - m1n);
        m0 = m0n; m1 = m1n;

        #pragma unroll
        for (int n = 0; n < 16; ++n) {
            oacc[n][0] *= a0; oacc[n][1] *= a0;
            oacc[n][2] *= a1; oacc[n][3] *= a1;
        }

        // ---- exp/repack interleaved with PV(j) ----
        const uint32_t VH = sb + SM_V + (uint32_t)(j & 1) * kStageB;
        const uint32_t VL = VH + kHalfB;
        float sum0 = 0.f, sum1 = 0.f;
        #pragma unroll
        for (int jj = 0; jj < 4; ++jj) {
            float* sA = cur[2 * jj];
            float* sB = cur[2 * jj + 1];
            sA[0] = __expf(sA[0] - m0n); sA[1] = __expf(sA[1] - m0n);
            sA[2] = __expf(sA[2] - m1n); sA[3] = __expf(sA[3] - m1n);
            sB[0] = __expf(sB[0] - m0n); sB[1] = __expf(sB[1] - m0n);
            sB[2] = __expf(sB[2] - m1n); sB[3] = __expf(sB[3] - m1n);
            sum0 += sA[0] + sA[1] + sB[0] + sB[1];
            sum1 += sA[2] + sA[3] + sB[2] + sB[3];

            uint32_t phi[4], plo[4];
            split2(sA[0], sA[1], phi[0], plo[0]);
            split2(sA[2], sA[3], phi[1], plo[1]);
            split2(sB[0], sB[1], phi[2], plo[2]);
            split2(sB[2], sB[3], phi[3], plo[3]);

            #pragma unroll
            for (int pp = 0; pp < 8; ++pp) {
                const uint32_t off = (uint32_t)((jj * 16 + b3 * 8 + w8) * kStrideB
                                                + (pp * 16 + b4 * 8) * 2);
                uint32_t vh0, vh1, vh2, vh3, vl0, vl1, vl2, vl3;
                ldsm_x4_t(vh0, vh1, vh2, vh3, VH + off);
                ldsm_x4_t(vl0, vl1, vl2, vl3, VL + off);
                mma_bf16(oacc[2*pp],   phi, vh0, vh1);
                mma_bf16(oacc[2*pp],   phi, vl0, vl1);
                mma_bf16(oacc[2*pp],   plo, vh0, vh1);
                mma_bf16(oacc[2*pp+1], phi, vh2, vh3);
                mma_bf16(oacc[2*pp+1], phi, vl2, vl3);
                mma_bf16(oacc[2*pp+1], plo, vh2, vh3);
            }
        }
        #pragma unroll
        for (int off = 1; off <= 2; off <<= 1) {
            sum0 += __shfl_xor_sync(0xffffffffu, sum0, off);
            sum1 += __shfl_xor_sync(0xffffffffu, sum1, off);
        }
        l0 = l0 * a0 + sum0;
        l1 = l1 * a1 + sum1;
    };

    for (int jj = 0; jj < kIters / 2; ++jj) {
        body(2 * jj,     saccA, saccB);
        body(2 * jj + 1, saccB, saccA);
    }

    // ---- epilogue ----
    const float dp = decode_scalar(dropout_p);
    const float inv0 = dp / l0, inv1 = dp / l1;
    const size_t row0 = (size_t)bh * kS + (size_t)qt * kBQ + (size_t)(wid * 16 + g);
    float* o0 = out + row0 * kD + 2 * t;
    float* o1 = o0 + (size_t)8 * kD;
    #pragma unroll
    for (int n = 0; n < 16; ++n) {
        *reinterpret_cast<float2*>(o0 + n * 8) = make_float2(oacc[n][0] * inv0, oacc[n][1] * inv0);
        *reinterpret_cast<float2*>(o1 + n * 8) = make_float2(oacc[n][2] * inv1, oacc[n][3] * inv1);
    }
}

extern "C" void kernel_launch(void* const* d_in, const int* in_sizes, int n_in,
                              void* d_out, int out_size) {
    const float* q  = (const float*)d_in[0];
    const float* k  = (const float*)d_in[1];
    const float* v  = (const float*)d_in[2];
    const float* sf = (const float*)d_in[3];
    const void*  dp = d_in[4];
    float* out = (float*)d_out;
    (void)in_sizes; (void)n_in; (void)out_size;

    dim3 cgrid(kIters, 32);
    convert_kv_kernel<<<cgrid, 256>>>(k, v);

    cudaFuncSetAttribute(flash_mma_kernel,
                         cudaFuncAttributeMaxDynamicSharedMemorySize, kSmemBytes);
    dim3 grid(kQTiles, 32);
    flash_mma_kernel<<<grid, kThreads, kSmemBytes>>>(q, sf, dp, out);
}

// round 9
// speedup vs baseline: 1.2550x; 1.2550x over previous
#include <cuda_runtime.h>
#include <cuda_bf16.h>
#include <cuda_fp16.h>
#include <cstdint>
#include <math.h>

// ============================================================
// R9: R4 skeleton exactly (cp.async double-buffer, SC in smem,
// one syncthreads/iter), with PV switched to fp16 2-term:
//   O += (P_hi + P_lo) * V_hi   (P exact via hi+lo, V fp16-rn)
// QK stays bf16 3-term. KV blob shrinks to khi,klo,vhi.
// ============================================================

constexpr int kS = 2048, kD = 128, kBQ = 128, kBK = 64;
constexpr int kThreads = 256;
constexpr int kIters = kS / kBK;            // 32
constexpr int kQTiles = kS / kBQ;           // 16

constexpr int kKVStrideB = 272;             // 136 elems/row (ldmatrix conflict-free)
constexpr int kKVTileB   = 64 * kKVStrideB; // 17408
constexpr int kBlobB     = 3 * kKVTileB;    // khi,klo,vhi = 52224
constexpr int kKVOps     = kBlobB / 16;     // 3264 cp.async 16B ops
constexpr int kScStrideB = 272;             // 68 floats
constexpr int kScTileB   = 128 * kScStrideB;// 34816

constexpr int SM_SC      = 2 * kBlobB;      // 104448
constexpr int kSmemBytes = SM_SC + 2 * kScTileB;  // 174080

// K/V pre-converted tile images: [bh][kt][khi|klo|vhi]
__device__ __align__(16) unsigned char g_kv[32u * 32u * (unsigned)kBlobB];

__device__ __forceinline__ uint32_t smem_u32(const void* p) {
    uint32_t a;
    asm("{ .reg .u64 t; cvta.to.shared.u64 t, %1; cvt.u32.u64 %0, t; }" : "=r"(a) : "l"(p));
    return a;
}
__device__ __forceinline__ void cp16(uint32_t dst, const void* src) {
    asm volatile("cp.async.cg.shared.global [%0], [%1], 16;" :: "r"(dst), "l"(src));
}
__device__ __forceinline__ void cp_commit() { asm volatile("cp.async.commit_group;" ::: "memory"); }
__device__ __forceinline__ void cp_wait0()  { asm volatile("cp.async.wait_group 0;" ::: "memory"); }

__device__ __forceinline__ void ldsm_x4(uint32_t& r0, uint32_t& r1, uint32_t& r2, uint32_t& r3,
                                        uint32_t addr) {
    asm volatile("ldmatrix.sync.aligned.m8n8.x4.shared.b16 {%0,%1,%2,%3}, [%4];"
        : "=r"(r0), "=r"(r1), "=r"(r2), "=r"(r3) : "r"(addr));
}
__device__ __forceinline__ void ldsm_x4_t(uint32_t& r0, uint32_t& r1, uint32_t& r2, uint32_t& r3,
                                          uint32_t addr) {
    asm volatile("ldmatrix.sync.aligned.m8n8.x4.trans.shared.b16 {%0,%1,%2,%3}, [%4];"
        : "=r"(r0), "=r"(r1), "=r"(r2), "=r"(r3) : "r"(addr));
}
__device__ __forceinline__ void mma_bf16(float* d, const uint32_t* a, uint32_t b0, uint32_t b1) {
    asm volatile("mma.sync.aligned.m16n8k16.row.col.f32.bf16.bf16.f32 "
        "{%0,%1,%2,%3}, {%4,%5,%6,%7}, {%8,%9}, {%0,%1,%2,%3};"
        : "+f"(d[0]), "+f"(d[1]), "+f"(d[2]), "+f"(d[3])
        : "r"(a[0]), "r"(a[1]), "r"(a[2]), "r"(a[3]), "r"(b0), "r"(b1));
}
__device__ __forceinline__ void mma_f16(float* d, const uint32_t* a, uint32_t b0, uint32_t b1) {
    asm volatile("mma.sync.aligned.m16n8k16.row.col.f32.f16.f16.f32 "
        "{%0,%1,%2,%3}, {%4,%5,%6,%7}, {%8,%9}, {%0,%1,%2,%3};"
        : "+f"(d[0]), "+f"(d[1]), "+f"(d[2]), "+f"(d[3])
        : "r"(a[0]), "r"(a[1]), "r"(a[2]), "r"(a[3]), "r"(b0), "r"(b1));
}
__device__ __forceinline__ uint32_t packbf(float a, float b) {
    __nv_bfloat162 t = __floats2bfloat162_rn(a, b);
    return *reinterpret_cast<uint32_t*>(&t);
}
// bf16 hi/lo split (QK path)
__device__ __forceinline__ void split2(float a, float b, uint32_t& hi, uint32_t& lo) {
    __nv_bfloat16 ah = __float2bfloat16(a), bh = __float2bfloat16(b);
    __nv_bfloat162 h; h.x = ah; h.y = bh;
    hi = *reinterpret_cast<uint32_t*>(&h);
    lo = packbf(a - __bfloat162float(ah), b - __bfloat162float(bh));
}
// fp16 hi/lo split (P for PV path)
__device__ __forceinline__ void split2h(float a, float b, uint32_t& hi, uint32_t& lo) {
    __half2 h = __floats2half2_rn(a, b);
    const float ra = a - __half2float(__low2half(h));
    const float rb = b - __half2float(__high2half(h));
    __half2 l = __floats2half2_rn(ra, rb);
    hi = *reinterpret_cast<uint32_t*>(&h);
    lo = *reinterpret_cast<uint32_t*>(&l);
}
__device__ __forceinline__ float decode_scalar(const void* p) {
    const int w = *reinterpret_cast<const int*>(p);
    if (w > -(1 << 23) && w < (1 << 23)) return (float)w;
    return __int_as_float(w);
}

// ---------------- precompute: K -> bf16 hi/lo, V -> fp16 hi (padded images) ----------------
__global__ __launch_bounds__(256, 4)
void convert_kv_kernel(const float* __restrict__ k, const float* __restrict__ v) {
    const int kt = (int)blockIdx.x, bh = (int)blockIdx.y, tid = (int)threadIdx.x;
    unsigned char* blob = g_kv + (size_t)(bh * 32 + kt) * kBlobB;
    const float* kgt = k + ((size_t)bh * kS + (size_t)kt * kBK) * kD;
    const float* vgt = v + ((size_t)bh * kS + (size_t)kt * kBK) * kD;
    #pragma unroll
    for (int it = 0; it < 8; ++it) {
        const int idx = it * 256 + tid;            // 2048 float4 per tile
        const int r = idx >> 5, c = (idx & 31) << 2;
        const int so = r * kKVStrideB + c * 2;
        {
            const float4 x = reinterpret_cast<const float4*>(kgt)[idx];
            uint32_t h0, l0, h1, l1;
            split2(x.x, x.y, h0, l0);
            split2(x.z, x.w, h1, l1);
            *reinterpret_cast<uint2*>(blob + so)            = make_uint2(h0, h1);
            *reinterpret_cast<uint2*>(blob + kKVTileB + so) = make_uint2(l0, l1);
        }
        {
            const float4 x = reinterpret_cast<const float4*>(vgt)[idx];
            __half2 v0 = __floats2half2_rn(x.x, x.y);
            __half2 v1 = __floats2half2_rn(x.z, x.w);
            *reinterpret_cast<uint2*>(blob + 2 * kKVTileB + so) =
                make_uint2(*reinterpret_cast<uint32_t*>(&v0), *reinterpret_cast<uint32_t*>(&v1));
        }
    }
}

// ---------------- main kernel ----------------
__global__ __launch_bounds__(kThreads, 1)
void flash_mma_kernel(const float* __restrict__ q,
                      const float* __restrict__ sf,
                      const void*  __restrict__ dropout_p,
                      float* __restrict__ out) {
    extern __shared__ char smem[];
    const uint32_t sb = smem_u32(smem);
    const int tid  = (int)threadIdx.x;
    const int wid  = tid >> 5;
    const int lane = tid & 31;
    const int g    = lane >> 2;
    const int t    = lane & 3;
    const int qt = (int)blockIdx.x;
    const int bh = (int)blockIdx.y;

    const float* sg = sf + (size_t)(qt * kBQ) * kS;

    auto issue_tile = [&](int kt, int stage) {
        const unsigned char* src = g_kv + (size_t)(bh * 32 + kt) * kBlobB;
        const uint32_t dkv = sb + (uint32_t)stage * kBlobB;
        #pragma unroll
        for (int i = 0; i < 13; ++i) {
            const int op = i * kThreads + tid;     // 3264 ops
            if (op < kKVOps) cp16(dkv + op * 16, src + (size_t)op * 16);
        }
        const unsigned char* ssc = reinterpret_cast<const unsigned char*>(sg + (size_t)kt * kBK);
        const uint32_t dsc = sb + SM_SC + (uint32_t)stage * kScTileB;
        #pragma unroll
        for (int i = 0; i < 8; ++i) {
            const int op = i * kThreads + tid;     // 2048 ops
            const int r = op >> 4, c = op & 15;
            cp16(dsc + (uint32_t)(r * kScStrideB + c * 16), ssc + (size_t)r * (kS * 4) + c * 16);
        }
        cp_commit();
    };
    issue_tile(0, 0);

    // ---- Q fragments (bf16 hi/lo) in registers ----
    const float* qg = q + ((size_t)bh * kS + (size_t)qt * kBQ) * kD;
    uint32_t qhi[8][4], qlo[8][4];
    {
        const float* rq0 = qg + (size_t)(wid * 16 + g) * kD;
        const float* rq8 = rq0 + 8 * kD;
        #pragma unroll
        for (int ks = 0; ks < 8; ++ks) {
            const int c = ks * 16 + 2 * t;
            const float2 f0 = *reinterpret_cast<const float2*>(rq0 + c);
            const float2 f1 = *reinterpret_cast<const float2*>(rq8 + c);
            const float2 f2 = *reinterpret_cast<const float2*>(rq0 + c + 8);
            const float2 f3 = *reinterpret_cast<const float2*>(rq8 + c + 8);
            split2(f0.x, f0.y, qhi[ks][0], qlo[ks][0]);
            split2(f1.x, f1.y, qhi[ks][1], qlo[ks][1]);
            split2(f2.x, f2.y, qhi[ks][2], qlo[ks][2]);
            split2(f3.x, f3.y, qhi[ks][3], qlo[ks][3]);
        }
    }

    float oacc[16][4];
    #pragma unroll
    for (int n = 0; n < 16; ++n)
        #pragma unroll
        for (int c = 0; c < 4; ++c) oacc[n][c] = 0.f;
    float m0 = -INFINITY, m1 = -INFINITY, l0 = 0.f, l1 = 0.f;

    const int w8 = lane & 7;
    const int b3 = (lane >> 3) & 1;
    const int b4 = (lane >> 4) & 1;

    for (int kt = 0; kt < kIters; ++kt) {
        cp_wait0();
        __syncthreads();     // tile kt visible; all warps done with the other stage
        if (kt + 1 < kIters) issue_tile(kt + 1, (kt + 1) & 1);

        const int st = kt & 1;
        const uint32_t KHI = sb + (uint32_t)st * kBlobB;
        const uint32_t KLO = KHI + kKVTileB;
        const uint32_t VHI = KHI + 2 * kKVTileB;

        // ---- S = Q K^T (bf16 3-term) ----
        float sacc[8][4];
        #pragma unroll
        for (int n = 0; n < 8; ++n)
            #pragma unroll
            for (int c = 0; c < 4; ++c) sacc[n][c] = 0.f;

        #pragma unroll
        for (int ks = 0; ks < 8; ++ks) {
            uint32_t bhi[8][2], blo[8][2];
            #pragma unroll
            for (int p = 0; p < 4; ++p) {
                const uint32_t off = (uint32_t)((p * 16 + b4 * 8 + w8) * kKVStrideB
                                                + (ks * 16 + b3 * 8) * 2);
                ldsm_x4(bhi[2*p][0], bhi[2*p][1], bhi[2*p+1][0], bhi[2*p+1][1], KHI + off);
                ldsm_x4(blo[2*p][0], blo[2*p][1], blo[2*p+1][0], blo[2*p+1][1], KLO + off);
            }
            #pragma unroll
            for (int n = 0; n < 8; ++n) {
                mma_bf16(sacc[n], qhi[ks], bhi[n][0], bhi[n][1]);
                mma_bf16(sacc[n], qhi[ks], blo[n][0], blo[n][1]);
                mma_bf16(sacc[n], qlo[ks], bhi[n][0], bhi[n][1]);
            }
        }

        // ---- scale (smem) + online softmax ----
        const int r0 = wid * 16 + g;
        const char* scb = smem + SM_SC + (size_t)st * kScTileB;
        const char* sc0 = scb + (size_t)r0 * kScStrideB + (size_t)(2 * t) * 4;
        const char* sc1 = sc0 + (size_t)8 * kScStrideB;
        float mx0 = -INFINITY, mx1 = -INFINITY;
        #pragma unroll
        for (int n = 0; n < 8; ++n) {
            const float2 s0 = *reinterpret_cast<const float2*>(sc0 + n * 32);
            const float2 s1 = *reinterpret_cast<const float2*>(sc1 + n * 32);
            sacc[n][0] *= s0.x; sacc[n][1] *= s0.y;
            sacc[n][2] *= s1.x; sacc[n][3] *= s1.y;
            mx0 = fmaxf(mx0, fmaxf(sacc[n][0], sacc[n][1]));
            mx1 = fmaxf(mx1, fmaxf(sacc[n][2], sacc[n][3]));
        }
        #pragma unroll
        for (int off = 1; off <= 2; off <<= 1) {
            mx0 = fmaxf(mx0, __shfl_xor_sync(0xffffffffu, mx0, off));
            mx1 = fmaxf(mx1, __shfl_xor_sync(0xffffffffu, mx1, off));
        }
        const float m0n = fmaxf(m0, mx0), m1n = fmaxf(m1, mx1);
        const float a0 = __expf(m0 - m0n), a1 = __expf(m1 - m1n);
        m0 = m0n; m1 = m1n;

        float sum0 = 0.f, sum1 = 0.f;
        #pragma unroll
        for (int n = 0; n < 8; ++n) {
            sacc[n][0] = __expf(sacc[n][0] - m0n);
            sacc[n][1] = __expf(sacc[n][1] - m0n);
            sacc[n][2] = __expf(sacc[n][2] - m1n);
            sacc[n][3] = __expf(sacc[n][3] - m1n);
            sum0 += sacc[n][0] + sacc[n][1];
            sum1 += sacc[n][2] + sacc[n][3];
        }
        #pragma unroll
        for (int off = 1; off <= 2; off <<= 1) {
            sum0 += __shfl_xor_sync(0xffffffffu, sum0, off);
            sum1 += __shfl_xor_sync(0xffffffffu, sum1, off);
        }
        l0 = l0 * a0 + sum0;  
        l1 = l1 * a1 + sum1;

        #pragma unroll
        for (int n = 0; n < 16; ++n) {
            oacc[n][0] *= a0; oacc[n][1] *= a0;
            oacc[n][2] *= a1; oacc[n][3] *= a1;
        }

        // ---- repack P (fp16 hi/lo) -> A-frags ----
        uint32_t phi[4][4], plo[4][4];
        #pragma unroll
        for (int j = 0; j < 4; ++j) {
            split2h(sacc[2*j][0],   sacc[2*j][1],   phi[j][0], plo[j][0]);
            split2h(sacc[2*j][2],   sacc[2*j][3],   phi[j][1], plo[j][1]);
            split2h(sacc[2*j+1][0], sacc[2*j+1][1], phi[j][2], plo[j][2]);
            split2h(sacc[2*j+1][2], sacc[2*j+1][3], phi[j][3], plo[j][3]);
        }

        // ---- O += (Phi + Plo) Vhi  (fp16 2-term) ----
        #pragma unroll
        for (int j = 0; j < 4; ++j) {
            #pragma unroll
            for (int pp = 0; pp < 8; ++pp) {
                const uint32_t off = (uint32_t)((j * 16 + b3 * 8 + w8) * kKVStrideB
                                                + (pp * 16 + b4 * 8) * 2);
                uint32_t vh0, vh1, vh2, vh3;
                ldsm_x4_t(vh0, vh1, vh2, vh3, VHI + off);
                mma_f16(oacc[2*pp],   phi[j], vh0, vh1);
                mma_f16(oacc[2*pp],   plo[j], vh0, vh1);
                mma_f16(oacc[2*pp+1], phi[j], vh2, vh3);
                mma_f16(oacc[2*pp+1], plo[j], vh2, vh3);
            }
        }
    }

    // ---- epilogue ----
    const float dp = decode_scalar(dropout_p);
    const float inv0 = dp / l0, inv1 = dp / l1;
    const size_t row0 = (size_t)bh * kS + (size_t)qt * kBQ + (size_t)(wid * 16 + g);
    float* o0 = out + row0 * kD + 2 * t;
    float* o1 = o0 + (size_t)8 * kD;
    #pragma unroll
    for (int n = 0; n < 16; ++n) {
        *reinterpret_cast<float2*>(o0 + n * 8) = make_float2(oacc[n][0] * inv0, oacc[n][1] * inv0);
        *reinterpret_cast<float2*>(o1 + n * 8) = make_float2(oacc[n][2] * inv1, oacc[n][3] * inv1);
    }
}

extern "C" void kernel_launch(void* const* d_in, const int* in_sizes, int n_in,
                              void* d_out, int out_size) {
    const float* q  = (const float*)d_in[0];
    const float* k  = (const float*)d_in[1];
    const float* v  = (const float*)d_in[2];
    const float* sf = (const float*)d_in[3];
    const void*  dp = d_in[4];
    float* out = (float*)d_out;
    (void)in_sizes; (void)n_in; (void)out_size;

    dim3 cgrid(kIters, 32);
    convert_kv_kernel<<<cgrid, 256>>>(k, v);

    cudaFuncSetAttribute(flash_mma_kernel,
                         cudaFuncAttributeMaxDynamicSharedMemorySize, kSmemBytes);
    dim3 grid(kQTiles, 32);   // 16 x 32 = 512 CTAs
    flash_mma_kernel<<<grid, kThreads, kSmemBytes>>>(q, sf, dp, out);
}

// round 10
// speedup vs baseline: 1.4826x; 1.1813x over previous
#include <cuda_runtime.h>
#include <cuda_bf16.h>
#include <cuda_fp16.h>
#include <cstdint>
#include <math.h>

// ============================================================
// R10: R9 skeleton (cp.async double-buffer, SC in smem, one
// syncthreads/iter). QK = bf16 3-term (unchanged). PV = single
// fp16 term:  O += P_fp16 * V_fp16.
//   error budget: P-quant 2^-12 + V-quant 2^-12 (independent)
//   -> ~3.4e-4 << 1e-3.
// ============================================================

constexpr int kS = 2048, kD = 128, kBQ = 128, kBK = 64;
constexpr int kThreads = 256;
constexpr int kIters = kS / kBK;            // 32
constexpr int kQTiles = kS / kBQ;           // 16

constexpr int kKVStrideB = 272;             // 136 elems/row (ldmatrix conflict-free)
constexpr int kKVTileB   = 64 * kKVStrideB; // 17408
constexpr int kBlobB     = 3 * kKVTileB;    // khi,klo,vhi = 52224
constexpr int kKVOps     = kBlobB / 16;     // 3264 cp.async 16B ops
constexpr int kScStrideB = 272;             // 68 floats
constexpr int kScTileB   = 128 * kScStrideB;// 34816

constexpr int SM_SC      = 2 * kBlobB;      // 104448
constexpr int kSmemBytes = SM_SC + 2 * kScTileB;  // 174080

// K/V pre-converted tile images: [bh][kt][khi|klo|vhi]
__device__ __align__(16) unsigned char g_kv[32u * 32u * (unsigned)kBlobB];

__device__ __forceinline__ uint32_t smem_u32(const void* p) {
    uint32_t a;
    asm("{ .reg .u64 t; cvta.to.shared.u64 t, %1; cvt.u32.u64 %0, t; }" : "=r"(a) : "l"(p));
    return a;
}
__device__ __forceinline__ void cp16(uint32_t dst, const void* src) {
    asm volatile("cp.async.cg.shared.global [%0], [%1], 16;" :: "r"(dst), "l"(src));
}
__device__ __forceinline__ void cp_commit() { asm volatile("cp.async.commit_group;" ::: "memory"); }
__device__ __forceinline__ void cp_wait0()  { asm volatile("cp.async.wait_group 0;" ::: "memory"); }

__device__ __forceinline__ void ldsm_x4(uint32_t& r0, uint32_t& r1, uint32_t& r2, uint32_t& r3,
                                        uint32_t addr) {
    asm volatile("ldmatrix.sync.aligned.m8n8.x4.shared.b16 {%0,%1,%2,%3}, [%4];"
        : "=r"(r0), "=r"(r1), "=r"(r2), "=r"(r3) : "r"(addr));
}
__device__ __forceinline__ void ldsm_x4_t(uint32_t& r0, uint32_t& r1, uint32_t& r2, uint32_t& r3,
                                          uint32_t addr) {
    asm volatile("ldmatrix.sync.aligned.m8n8.x4.trans.shared.b16 {%0,%1,%2,%3}, [%4];"
        : "=r"(r0), "=r"(r1), "=r"(r2), "=r"(r3) : "r"(addr));
}
__device__ __forceinline__ void mma_bf16(float* d, const uint32_t* a, uint32_t b0, uint32_t b1) {
    asm volatile("mma.sync.aligned.m16n8k16.row.col.f32.bf16.bf16.f32 "
        "{%0,%1,%2,%3}, {%4,%5,%6,%7}, {%8,%9}, {%0,%1,%2,%3};"
        : "+f"(d[0]), "+f"(d[1]), "+f"(d[2]), "+f"(d[3])
        : "r"(a[0]), "r"(a[1]), "r"(a[2]), "r"(a[3]), "r"(b0), "r"(b1));
}
__device__ __forceinline__ void mma_f16(float* d, const uint32_t* a, uint32_t b0, uint32_t b1) {
    asm volatile("mma.sync.aligned.m16n8k16.row.col.f32.f16.f16.f32 "
        "{%0,%1,%2,%3}, {%4,%5,%6,%7}, {%8,%9}, {%0,%1,%2,%3};"
        : "+f"(d[0]), "+f"(d[1]), "+f"(d[2]), "+f"(d[3])
        : "r"(a[0]), "r"(a[1]), "r"(a[2]), "r"(a[3]), "r"(b0), "r"(b1));
}
__device__ __forceinline__ uint32_t packbf(float a, float b) {
    __nv_bfloat162 t = __floats2bfloat162_rn(a, b);
    return *reinterpret_cast<uint32_t*>(&t);
}
__device__ __forceinline__ uint32_t packh(float a, float b) {
    __half2 t = __floats2half2_rn(a, b);
    return *reinterpret_cast<uint32_t*>(&t);
}
// bf16 hi/lo split (QK path)
__device__ __forceinline__ void split2(float a, float b, uint32_t& hi, uint32_t& lo) {
    __nv_bfloat16 ah = __float2bfloat16(a), bh = __float2bfloat16(b);
    __nv_bfloat162 h; h.x = ah; h.y = bh;
    hi = *reinterpret_cast<uint32_t*>(&h);
    lo = packbf(a - __bfloat162float(ah), b - __bfloat162float(bh));
}
__device__ __forceinline__ float decode_scalar(const void* p) {
    const int w = *reinterpret_cast<const int*>(p);
    if (w > -(1 << 23) && w < (1 << 23)) return (float)w;
    return __int_as_float(w);
}

// ---------------- precompute: K -> bf16 hi/lo, V -> fp16 (padded images) ----------------
__global__ __launch_bounds__(256, 4)
void convert_kv_kernel(const float* __restrict__ k, const float* __restrict__ v) {
    const int kt = (int)blockIdx.x, bh = (int)blockIdx.y, tid = (int)threadIdx.x;
    unsigned char* blob = g_kv + (size_t)(bh * 32 + kt) * kBlobB;
    const float* kgt = k + ((size_t)bh * kS + (size_t)kt * kBK) * kD;
    const float* vgt = v + ((size_t)bh * kS + (size_t)kt * kBK) * kD;
    #pragma unroll
    for (int it = 0; it < 8; ++it) {
        const int idx = it * 256 + tid;            // 2048 float4 per tile
        const int r = idx >> 5, c = (idx & 31) << 2;
        const int so = r * kKVStrideB + c * 2;
        {
            const float4 x = reinterpret_cast<const float4*>(kgt)[idx];
            uint32_t h0, l0, h1, l1;
            split2(x.x, x.y, h0, l0);
            split2(x.z, x.w, h1, l1);
            *reinterpret_cast<uint2*>(blob + so)            = make_uint2(h0, h1);
            *reinterpret_cast<uint2*>(blob + kKVTileB + so) = make_uint2(l0, l1);
        }
        {
            const float4 x = reinterpret_cast<const float4*>(vgt)[idx];
            *reinterpret_cast<uint2*>(blob + 2 * kKVTileB + so) =
                make_uint2(packh(x.x, x.y), packh(x.z, x.w));
        }
    }
}

// ---------------- main kernel ----------------
__global__ __launch_bounds__(kThreads, 1)
void flash_mma_kernel(const float* __restrict__ q,
                      const float* __restrict__ sf,
                      const void*  __restrict__ dropout_p,
                      float* __restrict__ out) {
    extern __shared__ char smem[];
    const uint32_t sb = smem_u32(smem);
    const int tid  = (int)threadIdx.x;
    const int wid  = tid >> 5;
    const int lane = tid & 31;
    const int g    = lane >> 2;
    const int t    = lane & 3;
    const int qt = (int)blockIdx.x;
    const int bh = (int)blockIdx.y;

    const float* sg = sf + (size_t)(qt * kBQ) * kS;

    auto issue_tile = [&](int kt, int stage) {
        const unsigned char* src = g_kv + (size_t)(bh * 32 + kt) * kBlobB;
        const uint32_t dkv = sb + (uint32_t)stage * kBlobB;
        #pragma unroll
        for (int i = 0; i < 13; ++i) {
            const int op = i * kThreads + tid;     // 3264 ops
            if (op < kKVOps) cp16(dkv + op * 16, src + (size_t)op * 16);
        }
        const unsigned char* ssc = reinterpret_cast<const unsigned char*>(sg + (size_t)kt * kBK);
        const uint32_t dsc = sb + SM_SC + (uint32_t)stage * kScTileB;
        #pragma unroll
        for (int i = 0; i < 8; ++i) {
            const int op = i * kThreads + tid;     // 2048 ops
            const int r = op >> 4, c = op & 15;
            cp16(dsc + (uint32_t)(r * kScStrideB + c * 16), ssc + (size_t)r * (kS * 4) + c * 16);
        }
        cp_commit();
    };
    issue_tile(0, 0);

    // ---- Q fragments (bf16 hi/lo) in registers ----
    const float* qg = q + ((size_t)bh * kS + (size_t)qt * kBQ) * kD;
    uint32_t qhi[8][4], qlo[8][4];
    {
        const float* rq0 = qg + (size_t)(wid * 16 + g) * kD;
        const float* rq8 = rq0 + 8 * kD;
        #pragma unroll
        for (int ks = 0; ks < 8; ++ks) {
            const int c = ks * 16 + 2 * t;
            const float2 f0 = *reinterpret_cast<const float2*>(rq0 + c);
            const float2 f1 = *reinterpret_cast<const float2*>(rq8 + c);
            const float2 f2 = *reinterpret_cast<const float2*>(rq0 + c + 8);
            const float2 f3 = *reinterpret_cast<const float2*>(rq8 + c + 8);
            split2(f0.x, f0.y, qhi[ks][0], qlo[ks][0]);
            split2(f1.x, f1.y, qhi[ks][1], qlo[ks][1]);
            split2(f2.x, f2.y, qhi[ks][2], qlo[ks][2]);
            split2(f3.x, f3.y, qhi[ks][3], qlo[ks][3]);
        }
    }

    float oacc[16][4];
    #pragma unroll
    for (int n = 0; n < 16; ++n)
        #pragma unroll
        for (int c = 0; c < 4; ++c) oacc[n][c] = 0.f;
    float m0 = -INFINITY, m1 = -INFINITY, l0 = 0.f, l1 = 0.f;

    const int w8 = lane & 7;
    const int b3 = (lane >> 3) & 1;
    const int b4 = (lane >> 4) & 1;

    for (int kt = 0; kt < kIters; ++kt) {
        cp_wait0();
        __syncthreads();     // tile kt visible; all warps done with the other stage
        if (kt + 1 < kIters) issue_tile(kt + 1, (kt + 1) & 1);

        const int st = kt & 1;
        const uint32_t KHI = sb + (uint32_t)st * kBlobB;
        const uint32_t KLO = KHI + kKVTileB;
        const uint32_t VHI = KHI + 2 * kKVTileB;

        // ---- S = Q K^T (bf16 3-term) ----
        float sacc[8][4];
        #pragma unroll
        for (int n = 0; n < 8; ++n)
            #pragma unroll
            for (int c = 0; c < 4; ++c) sacc[n][c] = 0.f;

        #pragma unroll
        for (int ks = 0; ks < 8; ++ks) {
            uint32_t bhi[8][2], blo[8][2];
            #pragma unroll
            for (int p = 0; p < 4; ++p) {
                const uint32_t off = (uint32_t)((p * 16 + b4 * 8 + w8) * kKVStrideB
                                                + (ks * 16 + b3 * 8) * 2);
                ldsm_x4(bhi[2*p][0], bhi[2*p][1], bhi[2*p+1][0], bhi[2*p+1][1], KHI + off);
                ldsm_x4(blo[2*p][0], blo[2*p][1], blo[2*p+1][0], blo[2*p+1][1], KLO + off);
            }
            #pragma unroll
            for (int n = 0; n < 8; ++n) {
                mma_bf16(sacc[n], qhi[ks], bhi[n][0], bhi[n][1]);
                mma_bf16(sacc[n], qhi[ks], blo[n][0], blo[n][1]);
                mma_bf16(sacc[n], qlo[ks], bhi[n][0], bhi[n][1]);
            }
        }

        // ---- scale (smem) + online softmax ----
        const int r0 = wid * 16 + g;
        const char* scb = smem + SM_SC + (size_t)st * kScTileB;
        const char* sc0 = scb + (size_t)r0 * kScStrideB + (size_t)(2 * t) * 4;
        const char* sc1 = sc0 + (size_t)8 * kScStrideB;
        float mx0 = -INFINITY, mx1 = -INFINITY;
        #pragma unroll
        for (int n = 0; n < 8; ++n) {
            const float2 s0 = *reinterpret_cast<const float2*>(sc0 + n * 32);
            const float2 s1 = *reinterpret_cast<const float2*>(sc1 + n * 32);
            sacc[n][0] *= s0.x; sacc[n][1] *= s0.y;
            sacc[n][2] *= s1.x; sacc[n][3] *= s1.y;
            mx0 = fmaxf(mx0, fmaxf(sacc[n][0], sacc[n][1]));
            mx1 = fmaxf(mx1, fmaxf(sacc[n][2], sacc[n][3]));
        }
        #pragma unroll
        for (int off = 1; off <= 2; off <<= 1) {
            mx0 = fmaxf(mx0, __shfl_xor_sync(0xffffffffu, mx0, off));
            mx1 = fmaxf(mx1, __shfl_xor_sync(0xffffffffu, mx1, off));
        }
        const float m0n = fmaxf(m0, mx0), m1n = fmaxf(m1, mx1);
        const float a0 = __expf(m0 - m0n), a1 = __expf(m1 - m1n);
        m0 = m0n; m1 = m1n;

        float sum0 = 0.f, sum1 = 0.f;
        #pragma unroll
        for (int n = 0; n < 8; ++n) {
            sacc[n][0] = __expf(sacc[n][0] - m0n);
            sacc[n][1] = __expf(sacc[n][1] - m0n);
            sacc[n][2] = __expf(sacc[n][2] - m1n);
            sacc[n][3] = __expf(sacc[n][3] - m1n);
            sum0 += sacc[n][0] + sacc[n][1];
            sum1 += sacc[n][2] + sacc[n][3];
        }
        #pragma unroll
        for (int off = 1; off <= 2; off <<= 1) {
            sum0 += __shfl_xor_sync(0xffffffffu, sum0, off);
            sum1 += __shfl_xor_sync(0xffffffffu, sum1, off);
        }
        l0 = l0 * a0 + sum0;
        l1 = l1 * a1 + sum1;

        #pragma unroll
        for (int n = 0; n < 16; ++n) {
            oacc[n][0] *= a0; oacc[n][1] *= a0;
            oacc[n][2] *= a1; oacc[n][3] *= a1;
        }

        // ---- repack P (fp16 single) -> A-frags ----
        uint32_t phi[4][4];
        #pragma unroll
        for (int j = 0; j < 4; ++j) {
            phi[j][0] = packh(sacc[2*j][0],   sacc[2*j][1]);
            phi[j][1] = packh(sacc[2*j][2],   sacc[2*j][3]);
            phi[j][2] = packh(sacc[2*j+1][0], sacc[2*j+1][1]);
            phi[j][3] = packh(sacc[2*j+1][2], sacc[2*j+1][3]);
        }

        // ---- O += P V  (single fp16 term) ----
        #pragma unroll
        for (int j = 0; j < 4; ++j) {
            #pragma unroll
            for (int pp = 0; pp < 8; ++pp) {
                const uint32_t off = (uint32_t)((j * 16 + b3 * 8 + w8) * kKVStrideB
                                                + (pp * 16 + b4 * 8) * 2);
                uint32_t vh0, vh1, vh2, vh3;
                ldsm_x4_t(vh0, vh1, vh2, vh3, VHI + off);
                mma_f16(oacc[2*pp],   phi[j], vh0, vh1);
                mma_f16(oacc[2*pp+1], phi[j], vh2, vh3);
            }
        }
    }

    // ---- epilogue ----
    const float dp = decode_scalar(dropout_p);
    const float inv0 = dp / l0, inv1 = dp / l1;
    const size_t row0 = (size_t)bh * kS + (size_t)qt * kBQ + (size_t)(wid * 16 + g);
    float* o0 = out + row0 * kD + 2 * t;
    float* o1 = o0 + (size_t)8 * kD;
    #pragma unroll
    for (int n = 0; n < 16; ++n) {
        *reinterpret_cast<float2*>(o0 + n * 8) = make_float2(oacc[n][0] * inv0, oacc[n][1] * inv0);
        *reinterpret_cast<float2*>(o1 + n * 8) = make_float2(oacc[n][2] * inv1, oacc[n][3] * inv1);
    }
}

extern "C" void kernel_launch(void* const* d_in, const int* in_sizes, int n_in,
                              void* d_out, int out_size) {
    const float* q  = (const float*)d_in[0];
    const float* k  = (const float*)d_in[1];
    const float* v  = (const float*)d_in[2];
    const float* sf = (const float*)d_in[3];
    const void*  dp = d_in[4];
    float* out = (float*)d_out;
    (void)in_sizes; (void)n_in; (void)out_size;

    dim3 cgrid(kIters, 32);
    convert_kv_kernel<<<cgrid, 256>>>(k, v);

    cudaFuncSetAttribute(flash_mma_kernel,
                         cudaFuncAttributeMaxDynamicSharedMemorySize, kSmemBytes);
    dim3 grid(kQTiles, 32);   // 16 x 32 = 512 CTAs
    flash_mma_kernel<<<grid, kThreads, kSmemBytes>>>(q, sf, dp, out);
}

// round 11
// speedup vs baseline: 1.6866x; 1.1376x over previous
#include <cuda_runtime.h>
#include <cuda_bf16.h>
#include <cuda_fp16.h>
#include <cstdint>
#include <math.h>

// ============================================================
// R11: R10 per-warp code, CTA split in two for SMSP desync.
//   - 128 threads/CTA (4 warps), BQ=64, grid 32x32=1024 CTAs
//   - __launch_bounds__(128, 2): 2 independent CTAs per SM ->
//     each SMSP runs 2 warps from DIFFERENT CTAs; their softmax
//     phases drift, keeping the tensor pipe fed.
//   - KV smem 2-stage ring per CTA (104448 B); SC from gmem/L2.
// QK = bf16 3-term, PV = single fp16 term (unchanged).
// ============================================================

constexpr int kS = 2048, kD = 128, kBQ = 64, kBK = 64;
constexpr int kThreads = 128;
constexpr int kIters = kS / kBK;            // 32
constexpr int kQTiles = kS / kBQ;           // 32

constexpr int kKVStrideB = 272;             // 136 elems/row (ldmatrix conflict-free)
constexpr int kKVTileB   = 64 * kKVStrideB; // 17408
constexpr int kBlobB     = 3 * kKVTileB;    // khi,klo,vhi = 52224
constexpr int kKVOps     = kBlobB / 16;     // 3264 cp.async 16B ops
constexpr int kSmemBytes = 2 * kBlobB;      // 104448 (two stages)

// K/V pre-converted tile images: [bh][kt][khi|klo|vhi]
__device__ __align__(16) unsigned char g_kv[32u * 32u * (unsigned)kBlobB];

__device__ __forceinline__ uint32_t smem_u32(const void* p) {
    uint32_t a;
    asm("{ .reg .u64 t; cvta.to.shared.u64 t, %1; cvt.u32.u64 %0, t; }" : "=r"(a) : "l"(p));
    return a;
}
__device__ __forceinline__ void cp16(uint32_t dst, const void* src) {
    asm volatile("cp.async.cg.shared.global [%0], [%1], 16;" :: "r"(dst), "l"(src));
}
__device__ __forceinline__ void cp_commit() { asm volatile("cp.async.commit_group;" ::: "memory"); }
__device__ __forceinline__ void cp_wait0()  { asm volatile("cp.async.wait_group 0;" ::: "memory"); }

__device__ __forceinline__ void ldsm_x4(uint32_t& r0, uint32_t& r1, uint32_t& r2, uint32_t& r3,
                                        uint32_t addr) {
    asm volatile("ldmatrix.sync.aligned.m8n8.x4.shared.b16 {%0,%1,%2,%3}, [%4];"
        : "=r"(r0), "=r"(r1), "=r"(r2), "=r"(r3) : "r"(addr));
}
__device__ __forceinline__ void ldsm_x4_t(uint32_t& r0, uint32_t& r1, uint32_t& r2, uint32_t& r3,
                                          uint32_t addr) {
    asm volatile("ldmatrix.sync.aligned.m8n8.x4.trans.shared.b16 {%0,%1,%2,%3}, [%4];"
        : "=r"(r0), "=r"(r1), "=r"(r2), "=r"(r3) : "r"(addr));
}
__device__ __forceinline__ void mma_bf16(float* d, const uint32_t* a, uint32_t b0, uint32_t b1) {
    asm volatile("mma.sync.aligned.m16n8k16.row.col.f32.bf16.bf16.f32 "
        "{%0,%1,%2,%3}, {%4,%5,%6,%7}, {%8,%9}, {%0,%1,%2,%3};"
        : "+f"(d[0]), "+f"(d[1]), "+f"(d[2]), "+f"(d[3])
        : "r"(a[0]), "r"(a[1]), "r"(a[2]), "r"(a[3]), "r"(b0), "r"(b1));
}
__device__ __forceinline__ void mma_f16(float* d, const uint32_t* a, uint32_t b0, uint32_t b1) {
    asm volatile("mma.sync.aligned.m16n8k16.row.col.f32.f16.f16.f32 "
        "{%0,%1,%2,%3}, {%4,%5,%6,%7}, {%8,%9}, {%0,%1,%2,%3};"
        : "+f"(d[0]), "+f"(d[1]), "+f"(d[2]), "+f"(d[3])
        : "r"(a[0]), "r"(a[1]), "r"(a[2]), "r"(a[3]), "r"(b0), "r"(b1));
}
__device__ __forceinline__ uint32_t packbf(float a, float b) {
    __nv_bfloat162 t = __floats2bfloat162_rn(a, b);
    return *reinterpret_cast<uint32_t*>(&t);
}
__device__ __forceinline__ uint32_t packh(float a, float b) {
    __half2 t = __floats2half2_rn(a, b);
    return *reinterpret_cast<uint32_t*>(&t);
}
// bf16 hi/lo split (QK path)
__device__ __forceinline__ void split2(float a, float b, uint32_t& hi, uint32_t& lo) {
    __nv_bfloat16 ah = __float2bfloat16(a), bh = __float2bfloat16(b);
    __nv_bfloat162 h; h.x = ah; h.y = bh;
    hi = *reinterpret_cast<uint32_t*>(&h);
    lo = packbf(a - __bfloat162float(ah), b - __bfloat162float(bh));
}
__device__ __forceinline__ float decode_scalar(const void* p) {
    const int w = *reinterpret_cast<const int*>(p);
    if (w > -(1 << 23) && w < (1 << 23)) return (float)w;
    return __int_as_float(w);
}

// ---------------- precompute: K -> bf16 hi/lo, V -> fp16 (padded images) ----------------
__global__ __launch_bounds__(256, 4)
void convert_kv_kernel(const float* __restrict__ k, const float* __restrict__ v) {
    const int kt = (int)blockIdx.x, bh = (int)blockIdx.y, tid = (int)threadIdx.x;
    unsigned char* blob = g_kv + (size_t)(bh * 32 + kt) * kBlobB;
    const float* kgt = k + ((size_t)bh * kS + (size_t)kt * kBK) * kD;
    const float* vgt = v + ((size_t)bh * kS + (size_t)kt * kBK) * kD;
    #pragma unroll
    for (int it = 0; it < 8; ++it) {
        const int idx = it * 256 + tid;            // 2048 float4 per tile
        const int r = idx >> 5, c = (idx & 31) << 2;
        const int so = r * kKVStrideB + c * 2;
        {
            const float4 x = reinterpret_cast<const float4*>(kgt)[idx];
            uint32_t h0, l0, h1, l1;
            split2(x.x, x.y, h0, l0);
            split2(x.z, x.w, h1, l1);
            *reinterpret_cast<uint2*>(blob + so)            = make_uint2(h0, h1);
            *reinterpret_cast<uint2*>(blob + kKVTileB + so) = make_uint2(l0, l1);
        }
        {
            const float4 x = reinterpret_cast<const float4*>(vgt)[idx];
            *reinterpret_cast<uint2*>(blob + 2 * kKVTileB + so) =
                make_uint2(packh(x.x, x.y), packh(x.z, x.w));
        }
    }
}

// ---------------- main kernel ----------------
__global__ __launch_bounds__(kThreads, 2)
void flash_mma_kernel(const float* __restrict__ q,
                      const float* __restrict__ sf,
                      const void*  __restrict__ dropout_p,
                      float* __restrict__ out) {
    extern __shared__ char smem[];
    const uint32_t sb = smem_u32(smem);
    const int tid  = (int)threadIdx.x;
    const int wid  = tid >> 5;          // 0..3
    const int lane = tid & 31;
    const int g    = lane >> 2;
    const int t    = lane & 3;
    const int qt = (int)blockIdx.x;
    const int bh = (int)blockIdx.y;

    auto issue_tile = [&](int kt, int stage) {
        const unsigned char* src = g_kv + (size_t)(bh * 32 + kt) * kBlobB;
        const uint32_t dkv = sb + (uint32_t)stage * kBlobB;
        #pragma unroll
        for (int i = 0; i < 26; ++i) {
            const int op = i * kThreads + tid;     // 3264 ops / 128 threads
            if (op < kKVOps) cp16(dkv + op * 16, src + (size_t)op * 16);
        }
        cp_commit();
    };
    issue_tile(0, 0);

    // ---- Q fragments (bf16 hi/lo) in registers ----
    const float* qg = q + ((size_t)bh * kS + (size_t)qt * kBQ) * kD;
    uint32_t qhi[8][4], qlo[8][4];
    {
        const float* rq0 = qg + (size_t)(wid * 16 + g) * kD;
        const float* rq8 = rq0 + 8 * kD;
        #pragma unroll
        for (int ks = 0; ks < 8; ++ks) {
            const int c = ks * 16 + 2 * t;
            const float2 f0 = *reinterpret_cast<const float2*>(rq0 + c);
            const float2 f1 = *reinterpret_cast<const float2*>(rq8 + c);
            const float2 f2 = *reinterpret_cast<const float2*>(rq0 + c + 8);
            const float2 f3 = *reinterpret_cast<const float2*>(rq8 + c + 8);
            split2(f0.x, f0.y, qhi[ks][0], qlo[ks][0]);
            split2(f1.x, f1.y, qhi[ks][1], qlo[ks][1]);
            split2(f2.x, f2.y, qhi[ks][2], qlo[ks][2]);
            split2(f3.x, f3.y, qhi[ks][3], qlo[ks][3]);
        }
    }

    float oacc[16][4];
    #pragma unroll
    for (int n = 0; n < 16; ++n)
        #pragma unroll
        for (int c = 0; c < 4; ++c) oacc[n][c] = 0.f;
    float m0 = -INFINITY, m1 = -INFINITY, l0 = 0.f, l1 = 0.f;

    const int w8 = lane & 7;
    const int b3 = (lane >> 3) & 1;
    const int b4 = (lane >> 4) & 1;

    // scale rows for this thread (gmem, L2-resident across 32 bh CTAs)
    const float* scr0 = sf + ((size_t)(qt * kBQ) + (size_t)(wid * 16 + g)) * kS + 2 * t;
    const float* scr1 = scr0 + (size_t)8 * kS;

    for (int kt = 0; kt < kIters; ++kt) {
        cp_wait0();
        __syncthreads();     // tile kt visible; all warps done with the other stage
        if (kt + 1 < kIters) issue_tile(kt + 1, (kt + 1) & 1);

        const int st = kt & 1;
        const uint32_t KHI = sb + (uint32_t)st * kBlobB;
        const uint32_t KLO = KHI + kKVTileB;
        const uint32_t VHI = KHI + 2 * kKVTileB;

        // ---- issue scale loads early (L2 latency overlaps QK) ----
        const float* scg0 = scr0 + (size_t)kt * kBK;
        const float* scg1 = scr1 + (size_t)kt * kBK;
        float2 sc0[8], sc1[8];
        #pragma unroll
        for (int n = 0; n < 8; ++n) {
            sc0[n] = *reinterpret_cast<const float2*>(scg0 + n * 8);
            sc1[n] = *reinterpret_cast<const float2*>(scg1 + n * 8);
        }

        // ---- S = Q K^T (bf16 3-term) ----
        float sacc[8][4];
        #pragma unroll
        for (int n = 0; n < 8; ++n)
            #pragma unroll
            for (int c = 0; c < 4; ++c) sacc[n][c] = 0.f;

        #pragma unroll
        for (int ks = 0; ks < 8; ++ks) {
            uint32_t bhi[8][2], blo[8][2];
            #pragma unroll
            for (int p = 0; p < 4; ++p) {
                const uint32_t off = (uint32_t)((p * 16 + b4 * 8 + w8) * kKVStrideB
                                                + (ks * 16 + b3 * 8) * 2);
                ldsm_x4(bhi[2*p][0], bhi[2*p][1], bhi[2*p+1][0], bhi[2*p+1][1], KHI + off);
                ldsm_x4(blo[2*p][0], blo[2*p][1], blo[2*p+1][0], blo[2*p+1][1], KLO + off);
            }
            #pragma unroll
            for (int n = 0; n < 8; ++n) {
                mma_bf16(sacc[n], qhi[ks], bhi[n][0], bhi[n][1]);
                mma_bf16(sacc[n], qhi[ks], blo[n][0], blo[n][1]);
                mma_bf16(sacc[n], qlo[ks], bhi[n][0], bhi[n][1]);
            }
        }

        // ---- scale + online softmax ----
        float mx0 = -INFINITY, mx1 = -INFINITY;
        #pragma unroll
        for (int n = 0; n < 8; ++n) {
            sacc[n][0] *= sc0[n].x; sacc[n][1] *= sc0[n].y;
            sacc[n][2] *= sc1[n].x; sacc[n][3] *= sc1[n].y;
            mx0 = fmaxf(mx0, fmaxf(sacc[n][0], sacc[n][1]));
            mx1 = fmaxf(mx1, fmaxf(sacc[n][2], sacc[n][3]));
        }
        #pragma unroll
        for (int off = 1; off <= 2; off <<= 1) {
            mx0 = fmaxf(mx0, __shfl_xor_sync(0xffffffffu, mx0, off));
            mx1 = fmaxf(mx1, __shfl_xor_sync(0xffffffffu, mx1, off));
        }
        const float m0n = fmaxf(m0, mx0), m1n = fmaxf(m1, mx1);
        const float a0 = __expf(m0 - m0n), a1 = __expf(m1 - m1n);
        m0 = m0n; m1 = m1n;

        float sum0 = 0.f, sum1 = 0.f;
        #pragma unroll
        for (int n = 0; n < 8; ++n) {
            sacc[n][0] = __expf(sacc[n][0] - m0n);
            sacc[n][1] = __expf(sacc[n][1] - m0n);
            sacc[n][2] = __expf(sacc[n][2] - m1n);
            sacc[n][3] = __expf(sacc[n][3] - m1n);
            sum0 += sacc[n][0] + sacc[n][1];
            sum1 += sacc[n][2] + sacc[n][3];
        }
        #pragma unroll
        for (int off = 1; off <= 2; off <<= 1) {
            sum0 += __shfl_xor_sync(0xffffffffu, sum0, off);
            sum1 += __shfl_xor_sync(0xffffffffu, sum1, off);
        }
        l0 = l0 * a0 + sum0;
        l1 = l1 * a1 + sum1;

        #pragma unroll
        for (int n = 0; n < 16; ++n) {
            oacc[n][0] *= a0; oacc[n][1] *= a0;
            oacc[n][2] *= a1; oacc[n][3] *= a1;
        }

        // ---- repack P (fp16 single) -> A-frags ----
        uint32_t phi[4][4];
        #pragma unroll
        for (int j = 0; j < 4; ++j) {
            phi[j][0] = packh(sacc[2*j][0],   sacc[2*j][1]);
            phi[j][1] = packh(sacc[2*j][2],   sacc[2*j][3]);
            phi[j][2] = packh(sacc[2*j+1][0], sacc[2*j+1][1]);
            phi[j][3] = packh(sacc[2*j+1][2], sacc[2*j+1][3]);
        }

        // ---- O += P V  (single fp16 term) ----
        #pragma unroll
        for (int j = 0; j < 4; ++j) {
            #pragma unroll
            for (int pp = 0; pp < 8; ++pp) {
                const uint32_t off = (uint32_t)((j * 16 + b3 * 8 + w8) * kKVStrideB
                                                + (pp * 16 + b4 * 8) * 2);
                uint32_t vh0, vh1, vh2, vh3;
                ldsm_x4_t(vh0, vh1, vh2, vh3, VHI + off);
                mma_f16(oacc[2*pp],   phi[j], vh0, vh1);
                mma_f16(oacc[2*pp+1], phi[j], vh2, vh3);
            }
        }
    }

    // ---- epilogue ----
    const float dp = decode_scalar(dropout_p);
    const float inv0 = dp / l0, inv1 = dp / l1;
    const size_t row0 = (size_t)bh * kS + (size_t)qt * kBQ + (size_t)(wid * 16 + g);
    float* o0 = out + row0 * kD + 2 * t;
    float* o1 = o0 + (size_t)8 * kD;
    #pragma unroll
    for (int n = 0; n < 16; ++n) {
        *reinterpret_cast<float2*>(o0 + n * 8) = make_float2(oacc[n][0] * inv0, oacc[n][1] * inv0);
        *reinterpret_cast<float2*>(o1 + n * 8) = make_float2(oacc[n][2] * inv1, oacc[n][3] * inv1);
    }
}

extern "C" void kernel_launch(void* const* d_in, const int* in_sizes, int n_in,
                              void* d_out, int out_size) {
    const float* q  = (const float*)d_in[0];
    const float* k  = (const float*)d_in[1];
    const float* v  = (const float*)d_in[2];
    const float* sf = (const float*)d_in[3];
    const void*  dp = d_in[4];
    float* out = (float*)d_out;
    (void)in_sizes; (void)n_in; (void)out_size;

    dim3 cgrid(kIters, 32);
    convert_kv_kernel<<<cgrid, 256>>>(k, v);

    cudaFuncSetAttribute(flash_mma_kernel,
                         cudaFuncAttributeMaxDynamicSharedMemorySize, kSmemBytes);
    dim3 grid(kQTiles, 32);   // 32 x 32 = 1024 CTAs, 2 per SM
    flash_mma_kernel<<<grid, kThreads, kSmemBytes>>>(q, sf, dp, out);
}

// round 12
// speedup vs baseline: 1.7694x; 1.0491x over previous
#include <cuda_runtime.h>
#include <cuda_bf16.h>
#include <cuda_fp16.h>
#include <cstdint>
#include <math.h>

// ============================================================
// R12: R11 structure (2 CTAs/SM desync, 2-stage cp.async ring,
// QK bf16 3-term, PV single fp16) + softmax critical-path cuts:
//   - per-lane l partial sums (row-sum shfls moved to epilogue)
//   - log2-domain softmax: scale tile pre-multiplied by log2(e),
//     raw ex2.approx instead of __expf (removes inner multiply)
// ============================================================

constexpr int kS = 2048, kD = 128, kBQ = 64, kBK = 64;
constexpr int kThreads = 128;
constexpr int kIters = kS / kBK;            // 32
constexpr int kQTiles = kS / kBQ;           // 32

constexpr int kKVStrideB = 272;             // 136 elems/row (ldmatrix conflict-free)
constexpr int kKVTileB   = 64 * kKVStrideB; // 17408
constexpr int kBlobB     = 3 * kKVTileB;    // khi,klo,vhi = 52224
constexpr int kKVOps     = kBlobB / 16;     // 3264 cp.async 16B ops
constexpr int kSmemBytes = 2 * kBlobB;      // 104448 (two stages)

__device__ __align__(16) unsigned char g_kv[32u * 32u * (unsigned)kBlobB];

__device__ __forceinline__ uint32_t smem_u32(const void* p) {
    uint32_t a;
    asm("{ .reg .u64 t; cvta.to.shared.u64 t, %1; cvt.u32.u64 %0, t; }" : "=r"(a) : "l"(p));
    return a;
}
__device__ __forceinline__ void cp16(uint32_t dst, const void* src) {
    asm volatile("cp.async.cg.shared.global [%0], [%1], 16;" :: "r"(dst), "l"(src));
}
__device__ __forceinline__ void cp_commit() { asm volatile("cp.async.commit_group;" ::: "memory"); }
__device__ __forceinline__ void cp_wait0()  { asm volatile("cp.async.wait_group 0;" ::: "memory"); }

__device__ __forceinline__ void ldsm_x4(uint32_t& r0, uint32_t& r1, uint32_t& r2, uint32_t& r3,
                                        uint32_t addr) {
    asm volatile("ldmatrix.sync.aligned.m8n8.x4.shared.b16 {%0,%1,%2,%3}, [%4];"
        : "=r"(r0), "=r"(r1), "=r"(r2), "=r"(r3) : "r"(addr));
}
__device__ __forceinline__ void ldsm_x4_t(uint32_t& r0, uint32_t& r1, uint32_t& r2, uint32_t& r3,
                                          uint32_t addr) {
    asm volatile("ldmatrix.sync.aligned.m8n8.x4.trans.shared.b16 {%0,%1,%2,%3}, [%4];"
        : "=r"(r0), "=r"(r1), "=r"(r2), "=r"(r3) : "r"(addr));
}
__device__ __forceinline__ void mma_bf16(float* d, const uint32_t* a, uint32_t b0, uint32_t b1) {
    asm volatile("mma.sync.aligned.m16n8k16.row.col.f32.bf16.bf16.f32 "
        "{%0,%1,%2,%3}, {%4,%5,%6,%7}, {%8,%9}, {%0,%1,%2,%3};"
        : "+f"(d[0]), "+f"(d[1]), "+f"(d[2]), "+f"(d[3])
        : "r"(a[0]), "r"(a[1]), "r"(a[2]), "r"(a[3]), "r"(b0), "r"(b1));
}
__device__ __forceinline__ void mma_f16(float* d, const uint32_t* a, uint32_t b0, uint32_t b1) {
    asm volatile("mma.sync.aligned.m16n8k16.row.col.f32.f16.f16.f32 "
        "{%0,%1,%2,%3}, {%4,%5,%6,%7}, {%8,%9}, {%0,%1,%2,%3};"
        : "+f"(d[0]), "+f"(d[1]), "+f"(d[2]), "+f"(d[3])
        : "r"(a[0]), "r"(a[1]), "r"(a[2]), "r"(a[3]), "r"(b0), "r"(b1));
}
__device__ __forceinline__ float ex2(float x) {
    float r;
    asm("ex2.approx.ftz.f32 %0, %1;" : "=f"(r) : "f"(x));
    return r;
}
__device__ __forceinline__ uint32_t packbf(float a, float b) {
    __nv_bfloat162 t = __floats2bfloat162_rn(a, b);
    return *reinterpret_cast<uint32_t*>(&t);
}
__device__ __forceinline__ uint32_t packh(float a, float b) {
    __half2 t = __floats2half2_rn(a, b);
    return *reinterpret_cast<uint32_t*>(&t);
}
__device__ __forceinline__ void split2(float a, float b, uint32_t& hi, uint32_t& lo) {
    __nv_bfloat16 ah = __float2bfloat16(a), bh = __float2bfloat16(b);
    __nv_bfloat162 h; h.x = ah; h.y = bh;
    hi = *reinterpret_cast<uint32_t*>(&h);
    lo = packbf(a - __bfloat162float(ah), b - __bfloat162float(bh));
}
__device__ __forceinline__ float decode_scalar(const void* p) {
    const int w = *reinterpret_cast<const int*>(p);
    if (w > -(1 << 23) && w < (1 << 23)) return (float)w;
    return __int_as_float(w);
}

// ---------------- precompute: K -> bf16 hi/lo, V -> fp16 (padded images) ----------------
__global__ __launch_bounds__(256, 4)
void convert_kv_kernel(const float* __restrict__ k, const float* __restrict__ v) {
    const int kt = (int)blockIdx.x, bh = (int)blockIdx.y, tid = (int)threadIdx.x;
    unsigned char* blob = g_kv + (size_t)(bh * 32 + kt) * kBlobB;
    const float* kgt = k + ((size_t)bh * kS + (size_t)kt * kBK) * kD;
    const float* vgt = v + ((size_t)bh * kS + (size_t)kt * kBK) * kD;
    #pragma unroll
    for (int it = 0; it < 8; ++it) {
        const int idx = it * 256 + tid;
        const int r = idx >> 5, c = (idx & 31) << 2;
        const int so = r * kKVStrideB + c * 2;
        {
            const float4 x = reinterpret_cast<const float4*>(kgt)[idx];
            uint32_t h0, l0, h1, l1;
            split2(x.x, x.y, h0, l0);
            split2(x.z, x.w, h1, l1);
            *reinterpret_cast<uint2*>(blob + so)            = make_uint2(h0, h1);
            *reinterpret_cast<uint2*>(blob + kKVTileB + so) = make_uint2(l0, l1);
        }
        {
            const float4 x = reinterpret_cast<const float4*>(vgt)[idx];
            *reinterpret_cast<uint2*>(blob + 2 * kKVTileB + so) =
                make_uint2(packh(x.x, x.y), packh(x.z, x.w));
        }
    }
}

// ---------------- main kernel ----------------
__global__ __launch_bounds__(kThreads, 2)
void flash_mma_kernel(const float* __restrict__ q,
                      const float* __restrict__ sf,
                      const void*  __restrict__ dropout_p,
                      float* __restrict__ out) {
    extern __shared__ char smem[];
    const uint32_t sb = smem_u32(smem);
    const int tid  = (int)threadIdx.x;
    const int wid  = tid >> 5;
    const int lane = tid & 31;
    const int g    = lane >> 2;
    const int t    = lane & 3;
    const int qt = (int)blockIdx.x;
    const int bh = (int)blockIdx.y;

    auto issue_tile = [&](int kt, int stage) {
        const unsigned char* src = g_kv + (size_t)(bh * 32 + kt) * kBlobB;
        const uint32_t dkv = sb + (uint32_t)stage * kBlobB;
        #pragma unroll
        for (int i = 0; i < 26; ++i) {
            const int op = i * kThreads + tid;
            if (op < kKVOps) cp16(dkv + op * 16, src + (size_t)op * 16);
        }
        cp_commit();
    };
    issue_tile(0, 0);

    // ---- Q fragments (bf16 hi/lo) in registers ----
    const float* qg = q + ((size_t)bh * kS + (size_t)qt * kBQ) * kD;
    uint32_t qhi[8][4], qlo[8][4];
    {
        const float* rq0 = qg + (size_t)(wid * 16 + g) * kD;
        const float* rq8 = rq0 + 8 * kD;
        #pragma unroll
        for (int ks = 0; ks < 8; ++ks) {
            const int c = ks * 16 + 2 * t;
            const float2 f0 = *reinterpret_cast<const float2*>(rq0 + c);
            const float2 f1 = *reinterpret_cast<const float2*>(rq8 + c);
            const float2 f2 = *reinterpret_cast<const float2*>(rq0 + c + 8);
            const float2 f3 = *reinterpret_cast<const float2*>(rq8 + c + 8);
            split2(f0.x, f0.y, qhi[ks][0], qlo[ks][0]);
            split2(f1.x, f1.y, qhi[ks][1], qlo[ks][1]);
            split2(f2.x, f2.y, qhi[ks][2], qlo[ks][2]);
            split2(f3.x, f3.y, qhi[ks][3], qlo[ks][3]);
        }
    }

    float oacc[16][4];
    #pragma unroll
    for (int n = 0; n < 16; ++n)
        #pragma unroll
        for (int c = 0; c < 4; ++c) oacc[n][c] = 0.f;
    // m in log2 units; l per-lane partial (reduced at epilogue)
    float m0 = -INFINITY, m1 = -INFINITY, l0 = 0.f, l1 = 0.f;

    const int w8 = lane & 7;
    const int b3 = (lane >> 3) & 1;
    const int b4 = (lane >> 4) & 1;

    constexpr float kLog2e = 1.4426950408889634f;
    const float* scr0 = sf + ((size_t)(qt * kBQ) + (size_t)(wid * 16 + g)) * kS + 2 * t;
    const float* scr1 = scr0 + (size_t)8 * kS;

    for (int kt = 0; kt < kIters; ++kt) {
        cp_wait0();
        __syncthreads();
        if (kt + 1 < kIters) issue_tile(kt + 1, (kt + 1) & 1);

        const int st = kt & 1;
        const uint32_t KHI = sb + (uint32_t)st * kBlobB;
        const uint32_t KLO = KHI + kKVTileB;
        const uint32_t VHI = KHI + 2 * kKVTileB;

        // ---- scale loads early (L2 latency overlaps QK); fold log2e in ----
        const float* scg0 = scr0 + (size_t)kt * kBK;
        const float* scg1 = scr1 + (size_t)kt * kBK;
        float2 sc0[8], sc1[8];
        #pragma unroll
        for (int n = 0; n < 8; ++n) {
            sc0[n] = *reinterpret_cast<const float2*>(scg0 + n * 8);
            sc1[n] = *reinterpret_cast<const float2*>(scg1 + n * 8);
            sc0[n].x *= kLog2e; sc0[n].y *= kLog2e;
            sc1[n].x *= kLog2e; sc1[n].y *= kLog2e;
        }

        // ---- S = Q K^T (bf16 3-term) ----
        float sacc[8][4];
        #pragma unroll
        for (int n = 0; n < 8; ++n)
            #pragma unroll
            for (int c = 0; c < 4; ++c) sacc[n][c] = 0.f;

        #pragma unroll
        for (int ks = 0; ks < 8; ++ks) {
            uint32_t bhi[8][2], blo[8][2];
            #pragma unroll
            for (int p = 0; p < 4; ++p) {
                const uint32_t off = (uint32_t)((p * 16 + b4 * 8 + w8) * kKVStrideB
                                                + (ks * 16 + b3 * 8) * 2);
                ldsm_x4(bhi[2*p][0], bhi[2*p][1], bhi[2*p+1][0], bhi[2*p+1][1], KHI + off);
                ldsm_x4(blo[2*p][0], blo[2*p][1], blo[2*p+1][0], blo[2*p+1][1], KLO + off);
            }
            #pragma unroll
            for (int n = 0; n < 8; ++n) {
                mma_bf16(sacc[n], qhi[ks], bhi[n][0], bhi[n][1]);
                mma_bf16(sacc[n], qhi[ks], blo[n][0], blo[n][1]);
                mma_bf16(sacc[n], qlo[ks], bhi[n][0], bhi[n][1]);
            }
        }

        // ---- scale (log2 domain) + online softmax ----
        float mx0 = -INFINITY, mx1 = -INFINITY;
        #pragma unroll
        for (int n = 0; n < 8; ++n) {
            sacc[n][0] *= sc0[n].x; sacc[n][1] *= sc0[n].y;
            sacc[n][2] *= sc1[n].x; sacc[n][3] *= sc1[n].y;
            mx0 = fmaxf(mx0, fmaxf(sacc[n][0], sacc[n][1]));
            mx1 = fmaxf(mx1, fmaxf(sacc[n][2], sacc[n][3]));
        }
        #pragma unroll
        for (int off = 1; off <= 2; off <<= 1) {
            mx0 = fmaxf(mx0, __shfl_xor_sync(0xffffffffu, mx0, off));
            mx1 = fmaxf(mx1, __shfl_xor_sync(0xffffffffu, mx1, off));
        }
        const float m0n = fmaxf(m0, mx0), m1n = fmaxf(m1, mx1);
        const float a0 = ex2(m0 - m0n), a1 = ex2(m1 - m1n);
        m0 = m0n; m1 = m1n;

        // per-lane partial sums (no shfl reduce in loop)
        float sum0 = 0.f, sum1 = 0.f;
        #pragma unroll
        for (int n = 0; n < 8; ++n) {
            sacc[n][0] = ex2(sacc[n][0] - m0n);
            sacc[n][1] = ex2(sacc[n][1] - m0n);
            sacc[n][2] = ex2(sacc[n][2] - m1n);
            sacc[n][3] = ex2(sacc[n][3] - m1n);
            sum0 += sacc[n][0] + sacc[n][1];
            sum1 += sacc[n][2] + sacc[n][3];
        }
        l0 = l0 * a0 + sum0;
        l1 = l1 * a1 + sum1;

        #pragma unroll
        for (int n = 0; n < 16; ++n) {
            oacc[n][0] *= a0; oacc[n][1] *= a0;
            oacc[n][2] *= a1; oacc[n][3] *= a1;
        }

        // ---- repack P (fp16 single) -> A-frags ----
        uint32_t phi[4][4];
        #pragma unroll
        for (int j = 0; j < 4; ++j) {
            phi[j][0] = packh(sacc[2*j][0],   sacc[2*j][1]);
            phi[j][1] = packh(sacc[2*j][2],   sacc[2*j][3]);
            phi[j][2] = packh(sacc[2*j+1][0], sacc[2*j+1][1]);
            phi[j][3] = packh(sacc[2*j+1][2], sacc[2*j+1][3]);
        }

        // ---- O += P V  (single fp16 term) ----
        #pragma unroll
        for (int j = 0; j < 4; ++j) {
            #pragma unroll
            for (int pp = 0; pp < 8; ++pp) {
                const uint32_t off = (uint32_t)((j * 16 + b3 * 8 + w8) * kKVStrideB
                                                + (pp * 16 + b4 * 8) * 2);
                uint32_t vh0, vh1, vh2, vh3;
                ldsm_x4_t(vh0, vh1, vh2, vh3, VHI + off);
                mma_f16(oacc[2*pp],   phi[j], vh0, vh1);
                mma_f16(oacc[2*pp+1], phi[j], vh2, vh3);
            }
        }
    }

    // ---- epilogue: reduce per-lane l across the 4 lanes of each row ----
    #pragma unroll
    for (int off = 1; off <= 2; off <<= 1) {
        l0 += __shfl_xor_sync(0xffffffffu, l0, off);
        l1 += __shfl_xor_sync(0xffffffffu, l1, off);
    }
    const float dp = decode_scalar(dropout_p);
    const float inv0 = dp / l0, inv1 = dp / l1;
    const size_t row0 = (size_t)bh * kS + (size_t)qt * kBQ + (size_t)(wid * 16 + g);
    float* o0 = out + row0 * kD + 2 * t;
    float* o1 = o0 + (size_t)8 * kD;
    #pragma unroll
    for (int n = 0; n < 16; ++n) {
        *reinterpret_cast<float2*>(o0 + n * 8) = make_float2(oacc[n][0] * inv0, oacc[n][1] * inv0);
        *reinterpret_cast<float2*>(o1 + n * 8) = make_float2(oacc[n][2] * inv1, oacc[n][3] * inv1);
    }
}

extern "C" void kernel_launch(void* const* d_in, const int* in_sizes, int n_in,
                              void* d_out, int out_size) {
    const float* q  = (const float*)d_in[0];
    const float* k  = (const float*)d_in[1];
    const float* v  = (const float*)d_in[2];
    const float* sf = (const float*)d_in[3];
    const void*  dp = d_in[4];
    float* out = (float*)d_out;
    (void)in_sizes; (void)n_in; (void)out_size;

    dim3 cgrid(kIters, 32);
    convert_kv_kernel<<<cgrid, 256>>>(k, v);

    cudaFuncSetAttribute(flash_mma_kernel,
                         cudaFuncAttributeMaxDynamicSharedMemorySize, kSmemBytes);
    dim3 grid(kQTiles, 32);   // 32 x 32 = 1024 CTAs, 2 per SM
    flash_mma_kernel<<<grid, kThreads, kSmemBytes>>>(q, sf, dp, out);
}

// round 13
// speedup vs baseline: 1.7875x; 1.0102x over previous
#include <cuda_runtime.h>
#include <cuda_bf16.h>
#include <cuda_fp16.h>
#include <cstdint>
#include <math.h>

// ============================================================
// R13: R12 inner loop (2 CTAs/SM, 2-stage cp.async ring, QK bf16
// 3-term, PV single fp16, log2 softmax, per-lane l) wrapped in a
// persistent work-stealing outer loop: 304 CTAs pop (qt,bh) tile
// tickets from a global atomic counter -> removes the 4-wave
// quantization (grid 1024 / 304 concurrent = 3.37 waves).
// ============================================================

constexpr int kS = 2048, kD = 128, kBQ = 64, kBK = 64;
constexpr int kThreads = 128;
constexpr int kIters = kS / kBK;            // 32
constexpr int kQTiles = kS / kBQ;           // 32
constexpr int kTiles  = kQTiles * 32;       // 1024 work units
constexpr int kPersistentCTAs = 304;        // 2 per SM x 152 SMs

constexpr int kKVStrideB = 272;             // 136 elems/row (ldmatrix conflict-free)
constexpr int kKVTileB   = 64 * kKVStrideB; // 17408
constexpr int kBlobB     = 3 * kKVTileB;    // khi,klo,vhi = 52224
constexpr int kKVOps     = kBlobB / 16;     // 3264 cp.async 16B ops
constexpr int kSmemBytes = 2 * kBlobB + 16; // 104464 (two stages + ticket bcast)

__device__ __align__(16) unsigned char g_kv[32u * 32u * (unsigned)kBlobB];
__device__ int g_ticket;

__device__ __forceinline__ uint32_t smem_u32(const void* p) {
    uint32_t a;
    asm("{ .reg .u64 t; cvta.to.shared.u64 t, %1; cvt.u32.u64 %0, t; }" : "=r"(a) : "l"(p));
    return a;
}
__device__ __forceinline__ void cp16(uint32_t dst, const void* src) {
    asm volatile("cp.async.cg.shared.global [%0], [%1], 16;" :: "r"(dst), "l"(src));
}
__device__ __forceinline__ void cp_commit() { asm volatile("cp.async.commit_group;" ::: "memory"); }
__device__ __forceinline__ void cp_wait0()  { asm volatile("cp.async.wait_group 0;" ::: "memory"); }

__device__ __forceinline__ void ldsm_x4(uint32_t& r0, uint32_t& r1, uint32_t& r2, uint32_t& r3,
                                        uint32_t addr) {
    asm volatile("ldmatrix.sync.aligned.m8n8.x4.shared.b16 {%0,%1,%2,%3}, [%4];"
        : "=r"(r0), "=r"(r1), "=r"(r2), "=r"(r3) : "r"(addr));
}
__device__ __forceinline__ void ldsm_x4_t(uint32_t& r0, uint32_t& r1, uint32_t& r2, uint32_t& r3,
                                          uint32_t addr) {
    asm volatile("ldmatrix.sync.aligned.m8n8.x4.trans.shared.b16 {%0,%1,%2,%3}, [%4];"
        : "=r"(r0), "=r"(r1), "=r"(r2), "=r"(r3) : "r"(addr));
}
__device__ __forceinline__ void mma_bf16(float* d, const uint32_t* a, uint32_t b0, uint32_t b1) {
    asm volatile("mma.sync.aligned.m16n8k16.row.col.f32.bf16.bf16.f32 "
        "{%0,%1,%2,%3}, {%4,%5,%6,%7}, {%8,%9}, {%0,%1,%2,%3};"
        : "+f"(d[0]), "+f"(d[1]), "+f"(d[2]), "+f"(d[3])
        : "r"(a[0]), "r"(a[1]), "r"(a[2]), "r"(a[3]), "r"(b0), "r"(b1));
}
__device__ __forceinline__ void mma_f16(float* d, const uint32_t* a, uint32_t b0, uint32_t b1) {
    asm volatile("mma.sync.aligned.m16n8k16.row.col.f32.f16.f16.f32 "
        "{%0,%1,%2,%3}, {%4,%5,%6,%7}, {%8,%9}, {%0,%1,%2,%3};"
        : "+f"(d[0]), "+f"(d[1]), "+f"(d[2]), "+f"(d[3])
        : "r"(a[0]), "r"(a[1]), "r"(a[2]), "r"(a[3]), "r"(b0), "r"(b1));
}
__device__ __forceinline__ float ex2(float x) {
    float r;
    asm("ex2.approx.ftz.f32 %0, %1;" : "=f"(r) : "f"(x));
    return r;
}
__device__ __forceinline__ uint32_t packbf(float a, float b) {
    __nv_bfloat162 t = __floats2bfloat162_rn(a, b);
    return *reinterpret_cast<uint32_t*>(&t);
}
__device__ __forceinline__ uint32_t packh(float a, float b) {
    __half2 t = __floats2half2_rn(a, b);
    return *reinterpret_cast<uint32_t*>(&t);
}
__device__ __forceinline__ void split2(float a, float b, uint32_t& hi, uint32_t& lo) {
    __nv_bfloat16 ah = __float2bfloat16(a), bh = __float2bfloat16(b);
    __nv_bfloat162 h; h.x = ah; h.y = bh;
    hi = *reinterpret_cast<uint32_t*>(&h);
    lo = packbf(a - __bfloat162float(ah), b - __bfloat162float(bh));
}
__device__ __forceinline__ float decode_scalar(const void* p) {
    const int w = *reinterpret_cast<const int*>(p);
    if (w > -(1 << 23) && w < (1 << 23)) return (float)w;
    return __int_as_float(w);
}

// ---------------- ticket reset ----------------
__global__ void reset_ticket_kernel() { g_ticket = 0; }

// ---------------- precompute: K -> bf16 hi/lo, V -> fp16 ----------------
__global__ __launch_bounds__(256, 4)
void convert_kv_kernel(const float* __restrict__ k, const float* __restrict__ v) {
    const int kt = (int)blockIdx.x, bh = (int)blockIdx.y, tid = (int)threadIdx.x;
    unsigned char* blob = g_kv + (size_t)(bh * 32 + kt) * kBlobB;
    const float* kgt = k + ((size_t)bh * kS + (size_t)kt * kBK) * kD;
    const float* vgt = v + ((size_t)bh * kS + (size_t)kt * kBK) * kD;
    #pragma unroll
    for (int it = 0; it < 8; ++it) {
        const int idx = it * 256 + tid;
        const int r = idx >> 5, c = (idx & 31) << 2;
        const int so = r * kKVStrideB + c * 2;
        {
            const float4 x = reinterpret_cast<const float4*>(kgt)[idx];
            uint32_t h0, l0, h1, l1;
            split2(x.x, x.y, h0, l0);
            split2(x.z, x.w, h1, l1);
            *reinterpret_cast<uint2*>(blob + so)            = make_uint2(h0, h1);
            *reinterpret_cast<uint2*>(blob + kKVTileB + so) = make_uint2(l0, l1);
        }
        {
            const float4 x = reinterpret_cast<const float4*>(vgt)[idx];
            *reinterpret_cast<uint2*>(blob + 2 * kKVTileB + so) =
                make_uint2(packh(x.x, x.y), packh(x.z, x.w));
        }
    }
}

// ---------------- main persistent kernel ----------------
__global__ __launch_bounds__(kThreads, 2)
void flash_mma_kernel(const float* __restrict__ q,
                      const float* __restrict__ sf,
                      const void*  __restrict__ dropout_p,
                      float* __restrict__ out) {
    extern __shared__ char smem[];
    const uint32_t sb = smem_u32(smem);
    int* ticket_sm = reinterpret_cast<int*>(smem + 2 * kBlobB);
    const int tid  = (int)threadIdx.x;
    const int wid  = tid >> 5;
    const int lane = tid & 31;
    const int g    = lane >> 2;
    const int t    = lane & 3;
    const int w8   = lane & 7;
    const int b3   = (lane >> 3) & 1;
    const int b4   = (lane >> 4) & 1;
    constexpr float kLog2e = 1.4426950408889634f;
    const float dp = decode_scalar(dropout_p);

    while (true) {
        // ---- pop a tile ticket ----
        if (tid == 0) *ticket_sm = atomicAdd(&g_ticket, 1);
        __syncthreads();
        const int tile = *ticket_sm;
        __syncthreads();
        if (tile >= kTiles) break;
        const int qt = tile & (kQTiles - 1);
        const int bh = tile >> 5;

        auto issue_tile = [&](int kt, int stage) {
            const unsigned char* src = g_kv + (size_t)(bh * 32 + kt) * kBlobB;
            const uint32_t dkv = sb + (uint32_t)stage * kBlobB;
            #pragma unroll
            for (int i = 0; i < 26; ++i) {
                const int op = i * kThreads + tid;
                if (op < kKVOps) cp16(dkv + op * 16, src + (size_t)op * 16);
            }
            cp_commit();
        };
        issue_tile(0, 0);

        // ---- Q fragments (bf16 hi/lo) in registers ----
        const float* qg = q + ((size_t)bh * kS + (size_t)qt * kBQ) * kD;
        uint32_t qhi[8][4], qlo[8][4];
        {
            const float* rq0 = qg + (size_t)(wid * 16 + g) * kD;
            const float* rq8 = rq0 + 8 * kD;
            #pragma unroll
            for (int ks = 0; ks < 8; ++ks) {
                const int c = ks * 16 + 2 * t;
                const float2 f0 = *reinterpret_cast<const float2*>(rq0 + c);
                const float2 f1 = *reinterpret_cast<const float2*>(rq8 + c);
                const float2 f2 = *reinterpret_cast<const float2*>(rq0 + c + 8);
                const float2 f3 = *reinterpret_cast<const float2*>(rq8 + c + 8);
                split2(f0.x, f0.y, qhi[ks][0], qlo[ks][0]);
                split2(f1.x, f1.y, qhi[ks][1], qlo[ks][1]);
                split2(f2.x, f2.y, qhi[ks][2], qlo[ks][2]);
                split2(f3.x, f3.y, qhi[ks][3], qlo[ks][3]);
            }
        }

        float oacc[16][4];
        #pragma unroll
        for (int n = 0; n < 16; ++n)
            #pragma unroll
            for (int c = 0; c < 4; ++c) oacc[n][c] = 0.f;
        float m0 = -INFINITY, m1 = -INFINITY, l0 = 0.f, l1 = 0.f;

        const float* scr0 = sf + ((size_t)(qt * kBQ) + (size_t)(wid * 16 + g)) * kS + 2 * t;
        const float* scr1 = scr0 + (size_t)8 * kS;

        for (int kt = 0; kt < kIters; ++kt) {
            cp_wait0();
            __syncthreads();
            if (kt + 1 < kIters) issue_tile(kt + 1, (kt + 1) & 1);

            const int st = kt & 1;
            const uint32_t KHI = sb + (uint32_t)st * kBlobB;
            const uint32_t KLO = KHI + kKVTileB;
            const uint32_t VHI = KHI + 2 * kKVTileB;

            // scale loads early (L2 latency overlaps QK); log2e folded in
            const float* scg0 = scr0 + (size_t)kt * kBK;
            const float* scg1 = scr1 + (size_t)kt * kBK;
            float2 sc0[8], sc1[8];
            #pragma unroll
            for (int n = 0; n < 8; ++n) {
                sc0[n] = *reinterpret_cast<const float2*>(scg0 + n * 8);
                sc1[n] = *reinterpret_cast<const float2*>(scg1 + n * 8);
                sc0[n].x *= kLog2e; sc0[n].y *= kLog2e;
                sc1[n].x *= kLog2e; sc1[n].y *= kLog2e;
            }

            // ---- S = Q K^T (bf16 3-term) ----
            float sacc[8][4];
            #pragma unroll
            for (int n = 0; n < 8; ++n)
                #pragma unroll
                for (int c = 0; c < 4; ++c) sacc[n][c] = 0.f;

            #pragma unroll
            for (int ks = 0; ks < 8; ++ks) {
                uint32_t bhi[8][2], blo[8][2];
                #pragma unroll
                for (int p = 0; p < 4; ++p) {
                    const uint32_t off = (uint32_t)((p * 16 + b4 * 8 + w8) * kKVStrideB
                                                    + (ks * 16 + b3 * 8) * 2);
                    ldsm_x4(bhi[2*p][0], bhi[2*p][1], bhi[2*p+1][0], bhi[2*p+1][1], KHI + off);
                    ldsm_x4(blo[2*p][0], blo[2*p][1], blo[2*p+1][0], blo[2*p+1][1], KLO + off);
                }
                #pragma unroll
                for (int n = 0; n < 8; ++n) {
                    mma_bf16(sacc[n], qhi[ks], bhi[n][0], bhi[n][1]);
                    mma_bf16(sacc[n], qhi[ks], blo[n][0], blo[n][1]);
                    mma_bf16(sacc[n], qlo[ks], bhi[n][0], bhi[n][1]);
                }
            }

            // ---- scale (log2 domain) + online softmax ----
            float mx0 = -INFINITY, mx1 = -INFINITY;
            #pragma unroll
            for (int n = 0; n < 8; ++n) {
                sacc[n][0] *= sc0[n].x; sacc[n][1] *= sc0[n].y;
                sacc[n][2] *= sc1[n].x; sacc[n][3] *= sc1[n].y;
                mx0 = fmaxf(mx0, fmaxf(sacc[n][0], sacc[n][1]));
                mx1 = fmaxf(mx1, fmaxf(sacc[n][2], sacc[n][3]));
            }
            #pragma unroll
            for (int off = 1; off <= 2; off <<= 1) {
                mx0 = fmaxf(mx0, __shfl_xor_sync(0xffffffffu, mx0, off));
                mx1 = fmaxf(mx1, __shfl_xor_sync(0xffffffffu, mx1, off));
            }
            const float m0n = fmaxf(m0, mx0), m1n = fmaxf(m1, mx1);
            const float a0 = ex2(m0 - m0n), a1 = ex2(m1 - m1n);
            m0 = m0n; m1 = m1n;

            float sum0 = 0.f, sum1 = 0.f;
            #pragma unroll
            for (int n = 0; n < 8; ++n) {
                sacc[n][0] = ex2(sacc[n][0] - m0n);
                sacc[n][1] = ex2(sacc[n][1] - m0n);
                sacc[n][2] = ex2(sacc[n][2] - m1n);
                sacc[n][3] = ex2(sacc[n][3] - m1n);
                sum0 += sacc[n][0] + sacc[n][1];
                sum1 += sacc[n][2] + sacc[n][3];
            }
            l0 = l0 * a0 + sum0;
            l1 = l1 * a1 + sum1;

            #pragma unroll
            for (int n = 0; n < 16; ++n) {
                oacc[n][0] *= a0; oacc[n][1] *= a0;
                oacc[n][2] *= a1; oacc[n][3] *= a1;
            }

            // ---- repack P (fp16) -> A-frags ----
            uint32_t phi[4][4];
            #pragma unroll
            for (int j = 0; j < 4; ++j) {
                phi[j][0] = packh(sacc[2*j][0],   sacc[2*j][1]);
                phi[j][1] = packh(sacc[2*j][2],   sacc[2*j][3]);
                phi[j][2] = packh(sacc[2*j+1][0], sacc[2*j+1][1]);
                phi[j][3] = packh(sacc[2*j+1][2], sacc[2*j+1][3]);
            }

            // ---- O += P V (single fp16 term) ----
            #pragma unroll
            for (int j = 0; j < 4; ++j) {
                #pragma unroll
                for (int pp = 0; pp < 8; ++pp) {
                    const uint32_t off = (uint32_t)((j * 16 + b3 * 8 + w8) * kKVStrideB
                                                    + (pp * 16 + b4 * 8) * 2);
                    uint32_t vh0, vh1, vh2, vh3;
                    ldsm_x4_t(vh0, vh1, vh2, vh3, VHI + off);
                    mma_f16(oacc[2*pp],   phi[j], vh0, vh1);
                    mma_f16(oacc[2*pp+1], phi[j], vh2, vh3);
                }
            }
        }

        // ---- per-tile epilogue ----
        float L0 = l0, L1 = l1;
        #pragma unroll
        for (int off = 1; off <= 2; off <<= 1) {
            L0 += __shfl_xor_sync(0xffffffffu, L0, off);
            L1 += __shfl_xor_sync(0xffffffffu, L1, off);
        }
        const float inv0 = dp / L0, inv1 = dp / L1;
        const size_t row0 = (size_t)bh * kS + (size_t)qt * kBQ + (size_t)(wid * 16 + g);
        float* o0 = out + row0 * kD + 2 * t;
        float* o1 = o0 + (size_t)8 * kD;
        #pragma unroll
        for (int n = 0; n < 16; ++n) {
            *reinterpret_cast<float2*>(o0 + n * 8) = make_float2(oacc[n][0] * inv0, oacc[n][1] * inv0);
            *reinterpret_cast<float2*>(o1 + n * 8) = make_float2(oacc[n][2] * inv1, oacc[n][3] * inv1);
        }
    }
}

extern "C" void kernel_launch(void* const* d_in, const int* in_sizes, int n_in,
                              void* d_out, int out_size) {
    const float* q  = (const float*)d_in[0];
    const float* k  = (const float*)d_in[1];
    const float* v  = (const float*)d_in[2];
    const float* sf = (const float*)d_in[3];
    const void*  dp = d_in[4];
    float* out = (float*)d_out;
    (void)in_sizes; (void)n_in; (void)out_size;

    reset_ticket_kernel<<<1, 1>>>();
    dim3 cgrid(kIters, 32);
    convert_kv_kernel<<<cgrid, 256>>>(k, v);

    cudaFuncSetAttribute(flash_mma_kernel,
                         cudaFuncAttributeMaxDynamicSharedMemorySize, kSmemBytes);
    flash_mma_kernel<<<kPersistentCTAs, kThreads, kSmemBytes>>>(q, sf, dp, out);
}